// round 6
// baseline (speedup 1.0000x reference)
#include <cuda_runtime.h>
#include <math.h>

#define BB 16
#define LL 320
#define DM 192
#define DI 384
#define DS 16
#define DR 12
#define DEPTH 24
#define NROWS (BB*LL)      /* 5120 */
#define NC 10
#define CL 32
#define LOG2E 1.4426950408889634f
#define EPSLN 1e-5f

typedef unsigned long long ull;

/* ---------------- scratch (static device globals; no allocation) -------- */
__device__ float g_hidden[NROWS*DM];
__device__ float g_res[NROWS*DM];
__device__ float g_hn[NROWS*DM];
__device__ float g_xz[NROWS*2*DI];
__device__ float g_xc[NROWS*DI];
__device__ float g_dbl[NROWS*44];
__device__ float g_dt[NROWS*DI];
__device__ float g_y[NROWS*DI];
__device__ float g_eend[BB*NC*DI*DS];
__device__ float g_S[BB*NC*DI];

__device__ __forceinline__ void fma2(ull &d, ull a, ull b) {
    asm("fma.rn.f32x2 %0, %1, %2, %3;" : "=l"(d) : "l"(a), "l"(b), "l"(d));
}
__device__ __forceinline__ ull pack2(float v) {
    ull d;
    asm("mov.b64 %0, {%1, %1};" : "=l"(d) : "f"(v));
    return d;
}
__device__ __forceinline__ void unpack2(ull v, float &lo, float &hi) {
    asm("mov.b64 {%0, %1}, %2;" : "=f"(lo), "=f"(hi) : "l"(v));
}

/* ---------------- patch embed + pos, zero residual ---------------------- */
__global__ __launch_bounds__(192) void patch_kernel(
    const float* __restrict__ ximg, const float* __restrict__ zimg,
    const float* __restrict__ pw, const float* __restrict__ pb,
    const float* __restrict__ posx, const float* __restrict__ posz,
    float* __restrict__ hidden, float* __restrict__ res)
{
    __shared__ float sp[4][768];
    int tg = blockIdx.x, tid = threadIdx.x;
    for (int i = 0; i < 4; i++) {
        int r = tg*4 + i, b = r / LL, t = r % LL;
        for (int c = tid; c < 768; c += 192) {
            int ch = c >> 8, p = c & 255, py = p >> 4, px = p & 15;
            float v;
            if (t < 64) {
                int ph = (t >> 3)*16 + py, pwi = (t & 7)*16 + px;
                v = zimg[((b*3 + ch)*128 + ph)*128 + pwi];
            } else {
                int tx = t - 64;
                int ph = (tx >> 4)*16 + py, pwi = (tx & 15)*16 + px;
                v = ximg[((b*3 + ch)*256 + ph)*256 + pwi];
            }
            sp[i][c] = v;
        }
    }
    __syncthreads();
    int d = tid;
    float a0 = 0.f, a1 = 0.f, a2 = 0.f, a3 = 0.f;
    const float* wr = pw + d*768;
    for (int c = 0; c < 768; c++) {
        float w = wr[c];
        a0 = fmaf(w, sp[0][c], a0);
        a1 = fmaf(w, sp[1][c], a1);
        a2 = fmaf(w, sp[2][c], a2);
        a3 = fmaf(w, sp[3][c], a3);
    }
    float accs[4] = {a0, a1, a2, a3};
    for (int i = 0; i < 4; i++) {
        int r = tg*4 + i, t = r % LL;
        float pos = (t < 64) ? posz[t*DM + d] : posx[(t - 64)*DM + d];
        hidden[r*DM + d] = accs[i] + pb[d] + pos;
        res[r*DM + d] = 0.f;
    }
}

/* ---------------- fused add + layernorm (used once, layer-0 prenorm) ---- */
__global__ __launch_bounds__(192) void addnorm_kernel(
    const float* __restrict__ hid, float* __restrict__ res,
    const float* __restrict__ w, const float* __restrict__ b,
    float* __restrict__ o, int write_res)
{
    int row = blockIdx.x, d = threadIdx.x;
    float v = hid[row*DM + d] + res[row*DM + d];
    if (write_res) res[row*DM + d] = v;
    float s = v, sq = v*v;
    #pragma unroll
    for (int off = 16; off > 0; off >>= 1) {
        s  += __shfl_down_sync(0xffffffffu, s,  off);
        sq += __shfl_down_sync(0xffffffffu, sq, off);
    }
    __shared__ float sh1[6], sh2[6];
    int wid = d >> 5, lane = d & 31;
    if (lane == 0) { sh1[wid] = s; sh2[wid] = sq; }
    __syncthreads();
    float ts = 0.f, tq = 0.f;
    #pragma unroll
    for (int i = 0; i < 6; i++) { ts += sh1[i]; tq += sh2[i]; }
    float mean = ts * (1.f/DM);
    float var  = tq * (1.f/DM) - mean*mean;
    float rs = rsqrtf(var + EPSLN);
    o[row*DM + d] = (v - mean) * rs * w[d] + b[d];
}

/* ---------------- f32x2 packed GEMM (in_proj) --------------------------- */
template<int BM, int BN, int BK, int TM, int TN, int KT>
__global__ __launch_bounds__((BM/TM)*(BN/TN)) void gemm2_kernel(
    const float* __restrict__ A, int lda,
    const float* __restrict__ W,
    float* __restrict__ C, int ldc)
{
    constexpr int NT  = (BM/TM)*(BN/TN);
    constexpr int BK4 = BK/4;
    constexpr int NA  = (BM*BK4 + NT - 1)/NT;
    constexpr int NW  = (BN*BK4 + NT - 1)/NT;
    constexpr int BMP = BM + 4, BNP = BN + 4;
    constexpr int T   = KT/BK;

    __shared__ __align__(16) float As[2][BK*BMP];
    __shared__ __align__(16) float Ws[2][BK*BNP];

    int tid = threadIdx.x;
    int bn = blockIdx.x * BN, bm = blockIdx.y * BM;
    int tx = tid % (BN/TN), ty = tid / (BN/TN);

    ull acc[TM][TN/2];
    #pragma unroll
    for (int i = 0; i < TM; i++)
        #pragma unroll
        for (int j = 0; j < TN/2; j++) acc[i][j] = 0ull;

    float4 ar[NA], wr[NW];

    #define LOAD_TILE(k0)                                                     \
        _Pragma("unroll")                                                     \
        for (int i = 0; i < NA; i++) {                                        \
            int e = tid + i*NT;                                               \
            if ((BM*BK4) % NT == 0 || e < BM*BK4) {                           \
                int m = e / BK4, kq = e % BK4;                                \
                ar[i] = *reinterpret_cast<const float4*>(                     \
                    &A[(size_t)(bm + m)*lda + (k0) + kq*4]);                  \
            }                                                                 \
        }                                                                     \
        _Pragma("unroll")                                                     \
        for (int i = 0; i < NW; i++) {                                        \
            int e = tid + i*NT;                                               \
            if ((BN*BK4) % NT == 0 || e < BN*BK4) {                           \
                int nn = e / BK4, kq = e % BK4;                               \
                wr[i] = *reinterpret_cast<const float4*>(                     \
                    &W[(size_t)(bn + nn)*KT + (k0) + kq*4]);                  \
            }                                                                 \
        }

    #define STORE_TILE(bf)                                                    \
        _Pragma("unroll")                                                     \
        for (int i = 0; i < NA; i++) {                                        \
            int e = tid + i*NT;                                               \
            if ((BM*BK4) % NT == 0 || e < BM*BK4) {                           \
                int m = e / BK4, kq = e % BK4;                                \
                As[bf][(kq*4+0)*BMP + m] = ar[i].x;                           \
                As[bf][(kq*4+1)*BMP + m] = ar[i].y;                           \
                As[bf][(kq*4+2)*BMP + m] = ar[i].z;                           \
                As[bf][(kq*4+3)*BMP + m] = ar[i].w;                           \
            }                                                                 \
        }                                                                     \
        _Pragma("unroll")                                                     \
        for (int i = 0; i < NW; i++) {                                        \
            int e = tid + i*NT;                                               \
            if ((BN*BK4) % NT == 0 || e < BN*BK4) {                           \
                int nn = e / BK4, kq = e % BK4;                               \
                Ws[bf][(kq*4+0)*BNP + nn] = wr[i].x;                          \
                Ws[bf][(kq*4+1)*BNP + nn] = wr[i].y;                          \
                Ws[bf][(kq*4+2)*BNP + nn] = wr[i].z;                          \
                Ws[bf][(kq*4+3)*BNP + nn] = wr[i].w;                          \
            }                                                                 \
        }

    LOAD_TILE(0)
    STORE_TILE(0)
    __syncthreads();

    for (int t = 0; t < T; t++) {
        int buf = t & 1;
        if (t + 1 < T) { LOAD_TILE((t+1)*BK) }
        #pragma unroll
        for (int kk = 0; kk < BK; kk++) {
            float av[TM];
            #pragma unroll
            for (int i4 = 0; i4 < TM/4; i4++)
                *reinterpret_cast<float4*>(&av[i4*4]) =
                    *reinterpret_cast<const float4*>(&As[buf][kk*BMP + ty*TM + i4*4]);
            ull ad[TM];
            #pragma unroll
            for (int i = 0; i < TM; i++) ad[i] = pack2(av[i]);
            ull bv[TN/2];
            #pragma unroll
            for (int j = 0; j < TN/2; j++)
                bv[j] = *reinterpret_cast<const ull*>(&Ws[buf][kk*BNP + tx*TN + j*2]);
            #pragma unroll
            for (int i = 0; i < TM; i++)
                #pragma unroll
                for (int j = 0; j < TN/2; j++)
                    fma2(acc[i][j], ad[i], bv[j]);
        }
        if (t + 1 < T) { STORE_TILE(buf ^ 1) }
        __syncthreads();
    }
    #undef LOAD_TILE
    #undef STORE_TILE

    #pragma unroll
    for (int i = 0; i < TM; i++) {
        int m = bm + ty*TM + i;
        float ov[TN];
        #pragma unroll
        for (int j = 0; j < TN/2; j++) unpack2(acc[i][j], ov[2*j], ov[2*j+1]);
        #pragma unroll
        for (int j4 = 0; j4 < TN/4; j4++)
            *reinterpret_cast<float4*>(&C[(size_t)m*ldc + bn + tx*TN + j4*4]) =
                *reinterpret_cast<const float4*>(&ov[j4*4]);
    }
}

/* ---------------- fused conv+silu -> x_proj -> dt_proj+softplus ---------- */
/* grid 160 blocks (32 rows each), 256 threads, ~145KB dynamic smem.        */
#define CPR 32
#define PADK 385
__global__ __launch_bounds__(256) void convproj_kernel(
    const float* __restrict__ xz, const float* __restrict__ cw,
    const float* __restrict__ cb, const float* __restrict__ xw,
    const float* __restrict__ dtw, const float* __restrict__ dtb,
    float* __restrict__ xc_g, float* __restrict__ dbl_g,
    float* __restrict__ dt_g)
{
    extern __shared__ float sm[];
    float* xc_s  = sm;                         /* CPR * PADK        */
    float* xw_s  = xc_s + CPR*PADK;            /* 48 * PADK         */
    float* dtw_s = xw_s + 48*PADK;             /* 384 * 13          */
    float* dbl_s = dtw_s + 384*13;             /* CPR * 13          */

    int tid = threadIdx.x, blk = blockIdx.x;
    int r0 = blk*CPR;
    int b = r0 / LL, c0 = r0 % LL;

    /* load weights (xw padded to 48 rows with zeros) */
    for (int e = tid; e < 48*384; e += 256) {
        int n = e / 384, k = e % 384;
        xw_s[n*PADK + k] = (n < 44) ? xw[n*384 + k] : 0.f;
    }
    for (int e = tid; e < 384*12; e += 256) {
        int n = e / 12, k = e % 12;
        dtw_s[n*13 + k] = dtw[e];
    }

    /* conv + silu */
    #pragma unroll
    for (int i = 0; i < (CPR*DI)/256; i++) {
        int e = tid + i*256;
        int m = e / DI, d = e % DI;
        int l = c0 + m;
        float acc = cb[d];
        #pragma unroll
        for (int j = 0; j < 4; j++) {
            int ls = l - 3 + j;
            if (ls >= 0)
                acc = fmaf(xz[(size_t)(b*LL + ls)*(2*DI) + d], cw[d*4 + j], acc);
        }
        float s = acc / (1.f + expf(-acc));
        xc_s[m*PADK + d] = s;
        xc_g[(size_t)(r0 + m)*DI + d] = s;
    }
    __syncthreads();

    /* x_proj: dbl[32][44] = xc_s[32][384] @ xw_s[48][384]^T  (16x16 threads) */
    {
        int tx = tid & 15, ty = tid >> 4;   /* tx: n-group (3 cols), ty: m-group (2 rows) */
        float accd[2][3];
        #pragma unroll
        for (int i = 0; i < 2; i++)
            #pragma unroll
            for (int j = 0; j < 3; j++) accd[i][j] = 0.f;
        #pragma unroll 4
        for (int k = 0; k < 384; k++) {
            float a0 = xc_s[(ty*2+0)*PADK + k];
            float a1 = xc_s[(ty*2+1)*PADK + k];
            #pragma unroll
            for (int j = 0; j < 3; j++) {
                float w = xw_s[(tx*3+j)*PADK + k];
                accd[0][j] = fmaf(a0, w, accd[0][j]);
                accd[1][j] = fmaf(a1, w, accd[1][j]);
            }
        }
        #pragma unroll
        for (int i = 0; i < 2; i++) {
            int m = ty*2 + i;
            #pragma unroll
            for (int j = 0; j < 3; j++) {
                int n = tx*3 + j;
                if (n < 44) dbl_g[(size_t)(r0 + m)*44 + n] = accd[i][j];
                if (n < 12) dbl_s[m*13 + n] = accd[i][j];
            }
        }
    }
    __syncthreads();

    /* dt_proj + bias + softplus */
    #pragma unroll
    for (int i = 0; i < (CPR*DI)/256; i++) {
        int e = tid + i*256;
        int m = e / DI, n = e % DI;
        float a = dtb[n];
        #pragma unroll
        for (int k = 0; k < 12; k++)
            a = fmaf(dbl_s[m*13 + k], dtw_s[n*13 + k], a);
        a = (a > 20.f) ? a : log1pf(expf(a));
        dt_g[(size_t)(r0 + m)*DI + n] = a;
    }
}

/* ---------------- scan pass 1: chunk-local scan ------------------------- */
__global__ __launch_bounds__(DI) void scan1_kernel(
    const float* __restrict__ dt, const float* __restrict__ xc,
    const float* __restrict__ dbl, const float* __restrict__ A_log,
    float* __restrict__ y, float* __restrict__ eend, float* __restrict__ S)
{
    int b = blockIdx.y, ck = blockIdx.x, d = threadIdx.x;
    __shared__ float sB[CL][DS], sC[CL][DS];
    for (int e = d; e < CL*DS; e += DI) {
        int l = e >> 4, n = e & 15;
        const float* row = dbl + (size_t)(b*LL + ck*CL + l)*44;
        sB[l][n] = row[12 + n];
        sC[l][n] = row[28 + n];
    }
    __syncthreads();
    float cn[DS], h[DS];
    const float* al = A_log + d*DS;
    #pragma unroll
    for (int n = 0; n < DS; n++) { cn[n] = -expf(al[n]) * LOG2E; h[n] = 0.f; }
    float Ss = 0.f;
    int base = (b*LL + ck*CL)*DI + d;
    for (int l = 0; l < CL; l++) {
        float dtv = dt[base + l*DI];
        float xcv = xc[base + l*DI];
        Ss += dtv;
        float u = dtv * xcv;
        float acc = 0.f;
        #pragma unroll
        for (int n = 0; n < DS; n++) {
            float e2 = exp2f(dtv * cn[n]);
            h[n] = fmaf(e2, h[n], u * sB[l][n]);
            acc = fmaf(h[n], sC[l][n], acc);
        }
        y[base + l*DI] = acc;
    }
    int si = (b*NC + ck)*DI + d;
    S[si] = Ss;
    #pragma unroll
    for (int n = 0; n < DS; n++) eend[(size_t)si*DS + n] = h[n];
}

/* ---------------- scan pass 2: inline carry + correction + gate --------- */
__global__ __launch_bounds__(DI) void scan3_kernel(
    const float* __restrict__ dt, const float* __restrict__ dbl,
    const float* __restrict__ A_log, const float* __restrict__ eend,
    const float* __restrict__ S,
    const float* __restrict__ xz, const float* __restrict__ xc,
    const float* __restrict__ Dsk, float* __restrict__ y)
{
    int b = blockIdx.y, ck = blockIdx.x, d = threadIdx.x;
    __shared__ float sC[CL][DS];
    for (int e = d; e < CL*DS; e += DI) {
        int l = e >> 4, n = e & 15;
        sC[l][n] = dbl[(size_t)(b*LL + ck*CL + l)*44 + 28 + n];
    }
    __syncthreads();
    float cn[DS], ci[DS];
    if (ck > 0) {
        const float* al = A_log + d*DS;
        #pragma unroll
        for (int n = 0; n < DS; n++) { cn[n] = -expf(al[n]) * LOG2E; ci[n] = 0.f; }
        for (int j = 0; j < ck; j++) {
            int si = (b*NC + j)*DI + d;
            float Sj = S[si];
            const float* ep = eend + (size_t)si*DS;
            #pragma unroll
            for (int n = 0; n < DS; n++)
                ci[n] = fmaf(exp2f(Sj * cn[n]), ci[n], ep[n]);
        }
    }
    float Dv = Dsk[d];
    int base = (b*LL + ck*CL)*DI + d;
    float tau = 0.f;
    for (int l = 0; l < CL; l++) {
        float dtv = dt[base + l*DI];
        tau += dtv;
        float yv = y[base + l*DI];
        if (ck > 0) {
            #pragma unroll
            for (int n = 0; n < DS; n++)
                yv = fmaf(exp2f(tau * cn[n]) * ci[n], sC[l][n], yv);
        }
        yv = fmaf(xc[base + l*DI], Dv, yv);
        int row = b*LL + ck*CL + l;
        float zv = xz[(size_t)row*(2*DI) + DI + d];
        yv *= zv / (1.f + expf(-zv));
        y[base + l*DI] = yv;
    }
}

/* ---------------- out_proj GEMM + fused add-residual + LayerNorm -------- */
/* BM=32, BN=192 (full row), BK=16, TM=4, TN=8, 192 threads, grid 160.     */
__global__ __launch_bounds__(192) void outproj_kernel(
    const float* __restrict__ A,          /* y, lda=384 */
    const float* __restrict__ W,          /* out_w layer: (192,384) */
    float* __restrict__ res,
    const float* __restrict__ lw, const float* __restrict__ lb,
    float* __restrict__ dst)
{
    constexpr int BMP = 36, BNP = 196, T = 24;
    __shared__ __align__(16) float As[2][16*BMP];
    __shared__ __align__(16) float Ws[2][16*BNP];
    __shared__ float sred[2][32][25];
    __shared__ float srow[32][2];

    int tid = threadIdx.x;
    int bm = blockIdx.x * 32;
    int tx = tid % 24, ty = tid / 24;

    ull acc[4][4];
    #pragma unroll
    for (int i = 0; i < 4; i++)
        #pragma unroll
        for (int j = 0; j < 4; j++) acc[i][j] = 0ull;

    float4 ar; float4 wr[4];

    #define OP_LOAD(k0)                                                       \
        if (tid < 128) {                                                      \
            int m = tid >> 2, kq = tid & 3;                                   \
            ar = *reinterpret_cast<const float4*>(                            \
                &A[(size_t)(bm + m)*DI + (k0) + kq*4]);                       \
        }                                                                     \
        _Pragma("unroll")                                                     \
        for (int i = 0; i < 4; i++) {                                         \
            int e = tid + i*192;                                              \
            int n = e >> 2, kq = e & 3;                                       \
            wr[i] = *reinterpret_cast<const float4*>(                         \
                &W[(size_t)n*DI + (k0) + kq*4]);                              \
        }

    #define OP_STORE(bf)                                                      \
        if (tid < 128) {                                                      \
            int m = tid >> 2, kq = tid & 3;                                   \
            As[bf][(kq*4+0)*BMP + m] = ar.x;                                  \
            As[bf][(kq*4+1)*BMP + m] = ar.y;                                  \
            As[bf][(kq*4+2)*BMP + m] = ar.z;                                  \
            As[bf][(kq*4+3)*BMP + m] = ar.w;                                  \
        }                                                                     \
        _Pragma("unroll")                                                     \
        for (int i = 0; i < 4; i++) {                                         \
            int e = tid + i*192;                                              \
            int n = e >> 2, kq = e & 3;                                       \
            Ws[bf][(kq*4+0)*BNP + n] = wr[i].x;                               \
            Ws[bf][(kq*4+1)*BNP + n] = wr[i].y;                               \
            Ws[bf][(kq*4+2)*BNP + n] = wr[i].z;                               \
            Ws[bf][(kq*4+3)*BNP + n] = wr[i].w;                               \
        }

    OP_LOAD(0)
    OP_STORE(0)
    __syncthreads();

    for (int t = 0; t < T; t++) {
        int buf = t & 1;
        if (t + 1 < T) { OP_LOAD((t+1)*16) }
        #pragma unroll
        for (int kk = 0; kk < 16; kk++) {
            float4 a4 = *reinterpret_cast<const float4*>(&As[buf][kk*BMP + ty*4]);
            float av[4] = {a4.x, a4.y, a4.z, a4.w};
            ull ad[4];
            #pragma unroll
            for (int i = 0; i < 4; i++) ad[i] = pack2(av[i]);
            ull bv[4];
            #pragma unroll
            for (int j = 0; j < 4; j++)
                bv[j] = *reinterpret_cast<const ull*>(&Ws[buf][kk*BNP + tx*8 + j*2]);
            #pragma unroll
            for (int i = 0; i < 4; i++)
                #pragma unroll
                for (int j = 0; j < 4; j++)
                    fma2(acc[i][j], ad[i], bv[j]);
        }
        if (t + 1 < T) { OP_STORE(buf ^ 1) }
        __syncthreads();
    }
    #undef OP_LOAD
    #undef OP_STORE

    /* epilogue: v = gemm + res; res = v; dst = LN(v) */
    float vr[4][8];
    #pragma unroll
    for (int i = 0; i < 4; i++) {
        int m = bm + ty*4 + i;
        float ov[8];
        #pragma unroll
        for (int j = 0; j < 4; j++) unpack2(acc[i][j], ov[2*j], ov[2*j+1]);
        float s = 0.f, q = 0.f;
        #pragma unroll
        for (int j = 0; j < 8; j++) {
            float v = ov[j] + res[(size_t)m*DM + tx*8 + j];
            vr[i][j] = v;
            s += v; q += v*v;
        }
        sred[0][ty*4 + i][tx] = s;
        sred[1][ty*4 + i][tx] = q;
    }
    __syncthreads();
    if (tid < 32) {
        float s = 0.f, q = 0.f;
        #pragma unroll
        for (int t = 0; t < 24; t++) { s += sred[0][tid][t]; q += sred[1][tid][t]; }
        float mean = s * (1.f/DM);
        float var  = q * (1.f/DM) - mean*mean;
        srow[tid][0] = mean;
        srow[tid][1] = rsqrtf(var + EPSLN);
    }
    __syncthreads();
    #pragma unroll
    for (int i = 0; i < 4; i++) {
        int rloc = ty*4 + i, m = bm + rloc;
        float mean = srow[rloc][0], rs = srow[rloc][1];
        #pragma unroll
        for (int j = 0; j < 8; j++) {
            int n = tx*8 + j;
            float v = vr[i][j];
            res[(size_t)m*DM + n] = v;
            dst[(size_t)m*DM + n] = (v - mean) * rs * lw[n] + lb[n];
        }
    }
}

/* ---------------- host driver ------------------------------------------- */
extern "C" void kernel_launch(void* const* d_in, const int* in_sizes, int n_in,
                              void* d_out, int out_size)
{
    const float* x_img   = (const float*)d_in[0];
    const float* z_img   = (const float*)d_in[1];
    const float* patch_w = (const float*)d_in[2];
    const float* patch_b = (const float*)d_in[3];
    const float* pos_x   = (const float*)d_in[4];
    const float* pos_z   = (const float*)d_in[5];
    const float* ln_w    = (const float*)d_in[6];
    const float* ln_b    = (const float*)d_in[7];
    const float* in_w    = (const float*)d_in[8];
    const float* conv_w  = (const float*)d_in[9];
    const float* conv_b  = (const float*)d_in[10];
    const float* xproj_w = (const float*)d_in[11];
    const float* dt_w    = (const float*)d_in[12];
    const float* dt_b    = (const float*)d_in[13];
    const float* A_log   = (const float*)d_in[14];
    const float* D_skip  = (const float*)d_in[15];
    const float* out_w   = (const float*)d_in[16];
    const float* fnorm_w = (const float*)d_in[17];
    const float* fnorm_b = (const float*)d_in[18];
    float* out = (float*)d_out;

    float *hidden, *res, *hn, *xz, *xc, *dbl, *dt, *y, *eend, *S;
    cudaGetSymbolAddress((void**)&hidden, g_hidden);
    cudaGetSymbolAddress((void**)&res,    g_res);
    cudaGetSymbolAddress((void**)&hn,     g_hn);
    cudaGetSymbolAddress((void**)&xz,     g_xz);
    cudaGetSymbolAddress((void**)&xc,     g_xc);
    cudaGetSymbolAddress((void**)&dbl,    g_dbl);
    cudaGetSymbolAddress((void**)&dt,     g_dt);
    cudaGetSymbolAddress((void**)&y,      g_y);
    cudaGetSymbolAddress((void**)&eend,   g_eend);
    cudaGetSymbolAddress((void**)&S,      g_S);

    const int CP_SMEM = (CPR*PADK + 48*PADK + 384*13 + CPR*13) * 4;
    cudaFuncSetAttribute(convproj_kernel,
                         cudaFuncAttributeMaxDynamicSharedMemorySize, CP_SMEM);

    patch_kernel<<<NROWS/4, 192>>>(x_img, z_img, patch_w, patch_b,
                                   pos_x, pos_z, hidden, res);
    addnorm_kernel<<<NROWS, 192>>>(hidden, res, ln_w, ln_b, hn, 1);

    for (int l = 0; l < DEPTH; l++) {
        /* in_proj: (5120,192) @ (768,192)^T -> xz (5120,768) */
        gemm2_kernel<64,128,16,8,8,192><<<dim3(6, 80), 128>>>(
            hn, DM, in_w + (size_t)l*2*DI*DM, xz, 2*DI);

        convproj_kernel<<<NROWS/CPR, 256, CP_SMEM>>>(
            xz, conv_w + l*DI*4, conv_b + l*DI,
            xproj_w + (size_t)l*44*DI, dt_w + (size_t)l*DI*DR, dt_b + l*DI,
            xc, dbl, dt);

        scan1_kernel<<<dim3(NC, BB), DI>>>(dt, xc, dbl, A_log + (size_t)l*DI*DS,
                                           y, eend, S);
        scan3_kernel<<<dim3(NC, BB), DI>>>(dt, dbl, A_log + (size_t)l*DI*DS,
                                           eend, S, xz, xc, D_skip + l*DI, y);

        /* out_proj + residual add + next-layer LN (fnorm on last layer) */
        const float* lw = (l < DEPTH-1) ? ln_w + (l+1)*DM : fnorm_w;
        const float* lb = (l < DEPTH-1) ? ln_b + (l+1)*DM : fnorm_b;
        float* dst = (l < DEPTH-1) ? hn : out;
        outproj_kernel<<<NROWS/32, 192>>>(y, out_w + (size_t)l*DM*DI,
                                          res, lw, lb, dst);
    }
}

// round 7
// speedup vs baseline: 1.1612x; 1.1612x over previous
#include <cuda_runtime.h>
#include <math.h>

#define BB 16
#define LL 320
#define DM 192
#define DI 384
#define DS 16
#define DR 12
#define DEPTH 24
#define NROWS (BB*LL)      /* 5120 */
#define NC 10
#define CL 32
#define LOG2E 1.4426950408889634f
#define EPSLN 1e-5f

typedef unsigned long long ull;

/* ---------------- scratch (static device globals; no allocation) -------- */
__device__ float g_hidden[NROWS*DM];
__device__ float g_res[NROWS*DM];
__device__ float g_hn[NROWS*DM];
__device__ float g_xz[NROWS*2*DI];
__device__ float g_xc[NROWS*DI];
__device__ float g_dbl[NROWS*44];
__device__ float g_dt[NROWS*DI];
__device__ float g_y[NROWS*DI];
__device__ float g_eend[BB*NC*DI*DS];
__device__ float g_S[BB*NC*DI];

__device__ __forceinline__ void fma2(ull &d, ull a, ull b) {
    asm("fma.rn.f32x2 %0, %1, %2, %3;" : "=l"(d) : "l"(a), "l"(b), "l"(d));
}
__device__ __forceinline__ ull pack2(float v) {
    ull d;
    asm("mov.b64 %0, {%1, %1};" : "=l"(d) : "f"(v));
    return d;
}
__device__ __forceinline__ void unpack2(ull v, float &lo, float &hi) {
    asm("mov.b64 {%0, %1}, %2;" : "=f"(lo), "=f"(hi) : "l"(v));
}

/* ---------------- patch embed + pos, zero residual ---------------------- */
__global__ __launch_bounds__(192) void patch_kernel(
    const float* __restrict__ ximg, const float* __restrict__ zimg,
    const float* __restrict__ pw, const float* __restrict__ pb,
    const float* __restrict__ posx, const float* __restrict__ posz,
    float* __restrict__ hidden, float* __restrict__ res)
{
    __shared__ float sp[4][768];
    int tg = blockIdx.x, tid = threadIdx.x;
    for (int i = 0; i < 4; i++) {
        int r = tg*4 + i, b = r / LL, t = r % LL;
        for (int c = tid; c < 768; c += 192) {
            int ch = c >> 8, p = c & 255, py = p >> 4, px = p & 15;
            float v;
            if (t < 64) {
                int ph = (t >> 3)*16 + py, pwi = (t & 7)*16 + px;
                v = zimg[((b*3 + ch)*128 + ph)*128 + pwi];
            } else {
                int tx = t - 64;
                int ph = (tx >> 4)*16 + py, pwi = (tx & 15)*16 + px;
                v = ximg[((b*3 + ch)*256 + ph)*256 + pwi];
            }
            sp[i][c] = v;
        }
    }
    __syncthreads();
    int d = tid;
    float a0 = 0.f, a1 = 0.f, a2 = 0.f, a3 = 0.f;
    const float* wr = pw + d*768;
    for (int c = 0; c < 768; c++) {
        float w = wr[c];
        a0 = fmaf(w, sp[0][c], a0);
        a1 = fmaf(w, sp[1][c], a1);
        a2 = fmaf(w, sp[2][c], a2);
        a3 = fmaf(w, sp[3][c], a3);
    }
    float accs[4] = {a0, a1, a2, a3};
    for (int i = 0; i < 4; i++) {
        int r = tg*4 + i, t = r % LL;
        float pos = (t < 64) ? posz[t*DM + d] : posx[(t - 64)*DM + d];
        hidden[r*DM + d] = accs[i] + pb[d] + pos;
        res[r*DM + d] = 0.f;
    }
}

/* ---------------- fused add + layernorm (layer-0 prenorm only) ---------- */
__global__ __launch_bounds__(192) void addnorm_kernel(
    const float* __restrict__ hid, float* __restrict__ res,
    const float* __restrict__ w, const float* __restrict__ b,
    float* __restrict__ o, int write_res)
{
    int row = blockIdx.x, d = threadIdx.x;
    float v = hid[row*DM + d] + res[row*DM + d];
    if (write_res) res[row*DM + d] = v;
    float s = v, sq = v*v;
    #pragma unroll
    for (int off = 16; off > 0; off >>= 1) {
        s  += __shfl_down_sync(0xffffffffu, s,  off);
        sq += __shfl_down_sync(0xffffffffu, sq, off);
    }
    __shared__ float sh1[6], sh2[6];
    int wid = d >> 5, lane = d & 31;
    if (lane == 0) { sh1[wid] = s; sh2[wid] = sq; }
    __syncthreads();
    float ts = 0.f, tq = 0.f;
    #pragma unroll
    for (int i = 0; i < 6; i++) { ts += sh1[i]; tq += sh2[i]; }
    float mean = ts * (1.f/DM);
    float var  = tq * (1.f/DM) - mean*mean;
    float rs = rsqrtf(var + EPSLN);
    o[row*DM + d] = (v - mean) * rs * w[d] + b[d];
}

/* ---------------- f32x2 packed GEMM: C[M,N] = A[M,K] @ W[N,K]^T ---------- */
/* EP: 0 = none, 1 = +bias then softplus. NG: guard N (loads + stores).     */
template<int BM, int BN, int BK, int TM, int TN, int KT, int EP, bool NG>
__global__ __launch_bounds__((BM/TM)*(BN/TN)) void gemm2_kernel(
    const float* __restrict__ A, int lda,
    const float* __restrict__ W,
    float* __restrict__ C, int ldc,
    int N, const float* __restrict__ bias)
{
    constexpr int NT  = (BM/TM)*(BN/TN);
    constexpr int BK4 = BK/4;
    constexpr int NA  = (BM*BK4 + NT - 1)/NT;
    constexpr int NW  = (BN*BK4 + NT - 1)/NT;
    constexpr int BMP = BM + 4, BNP = BN + 4;
    constexpr int T   = KT/BK;

    __shared__ __align__(16) float As[2][BK*BMP];
    __shared__ __align__(16) float Ws[2][BK*BNP];

    int tid = threadIdx.x;
    int bn = blockIdx.x * BN, bm = blockIdx.y * BM;
    int tx = tid % (BN/TN), ty = tid / (BN/TN);

    ull acc[TM][TN/2];
    #pragma unroll
    for (int i = 0; i < TM; i++)
        #pragma unroll
        for (int j = 0; j < TN/2; j++) acc[i][j] = 0ull;

    float4 ar[NA], wr[NW];

    #define LOAD_TILE(k0)                                                     \
        _Pragma("unroll")                                                     \
        for (int i = 0; i < NA; i++) {                                        \
            int e = tid + i*NT;                                               \
            if ((BM*BK4) % NT == 0 || e < BM*BK4) {                           \
                int m = e / BK4, kq = e % BK4;                                \
                ar[i] = *reinterpret_cast<const float4*>(                     \
                    &A[(size_t)(bm + m)*lda + (k0) + kq*4]);                  \
            }                                                                 \
        }                                                                     \
        _Pragma("unroll")                                                     \
        for (int i = 0; i < NW; i++) {                                        \
            int e = tid + i*NT;                                               \
            if ((BN*BK4) % NT == 0 || e < BN*BK4) {                           \
                int nn = e / BK4, kq = e % BK4;                               \
                if (NG && bn + nn >= N) wr[i] = make_float4(0.f,0.f,0.f,0.f); \
                else wr[i] = *reinterpret_cast<const float4*>(                \
                    &W[(size_t)(bn + nn)*KT + (k0) + kq*4]);                  \
            }                                                                 \
        }

    #define STORE_TILE(bf)                                                    \
        _Pragma("unroll")                                                     \
        for (int i = 0; i < NA; i++) {                                        \
            int e = tid + i*NT;                                               \
            if ((BM*BK4) % NT == 0 || e < BM*BK4) {                           \
                int m = e / BK4, kq = e % BK4;                                \
                As[bf][(kq*4+0)*BMP + m] = ar[i].x;                           \
                As[bf][(kq*4+1)*BMP + m] = ar[i].y;                           \
                As[bf][(kq*4+2)*BMP + m] = ar[i].z;                           \
                As[bf][(kq*4+3)*BMP + m] = ar[i].w;                           \
            }                                                                 \
        }                                                                     \
        _Pragma("unroll")                                                     \
        for (int i = 0; i < NW; i++) {                                        \
            int e = tid + i*NT;                                               \
            if ((BN*BK4) % NT == 0 || e < BN*BK4) {                           \
                int nn = e / BK4, kq = e % BK4;                               \
                Ws[bf][(kq*4+0)*BNP + nn] = wr[i].x;                          \
                Ws[bf][(kq*4+1)*BNP + nn] = wr[i].y;                          \
                Ws[bf][(kq*4+2)*BNP + nn] = wr[i].z;                          \
                Ws[bf][(kq*4+3)*BNP + nn] = wr[i].w;                          \
            }                                                                 \
        }

    LOAD_TILE(0)
    STORE_TILE(0)
    __syncthreads();

    for (int t = 0; t < T; t++) {
        int buf = t & 1;
        if (t + 1 < T) { LOAD_TILE((t+1)*BK) }
        #pragma unroll
        for (int kk = 0; kk < BK; kk++) {
            float av[TM];
            #pragma unroll
            for (int i4 = 0; i4 < TM/4; i4++)
                *reinterpret_cast<float4*>(&av[i4*4]) =
                    *reinterpret_cast<const float4*>(&As[buf][kk*BMP + ty*TM + i4*4]);
            ull ad[TM];
            #pragma unroll
            for (int i = 0; i < TM; i++) ad[i] = pack2(av[i]);
            ull bv[TN/2];
            #pragma unroll
            for (int j = 0; j < TN/2; j++)
                bv[j] = *reinterpret_cast<const ull*>(&Ws[buf][kk*BNP + tx*TN + j*2]);
            #pragma unroll
            for (int i = 0; i < TM; i++)
                #pragma unroll
                for (int j = 0; j < TN/2; j++)
                    fma2(acc[i][j], ad[i], bv[j]);
        }
        if (t + 1 < T) { STORE_TILE(buf ^ 1) }
        __syncthreads();
    }
    #undef LOAD_TILE
    #undef STORE_TILE

    #pragma unroll
    for (int i = 0; i < TM; i++) {
        int m = bm + ty*TM + i;
        float ov[TN];
        #pragma unroll
        for (int j = 0; j < TN/2; j++) unpack2(acc[i][j], ov[2*j], ov[2*j+1]);
        if (EP == 1) {
            #pragma unroll
            for (int jj = 0; jj < TN; jj++) {
                int n = bn + tx*TN + jj;
                float v = ov[jj] + bias[n];
                ov[jj] = (v > 20.f) ? v : log1pf(expf(v));
            }
        }
        if (NG) {
            #pragma unroll
            for (int jj = 0; jj < TN; jj++) {
                int n = bn + tx*TN + jj;
                if (n < N) C[(size_t)m*ldc + n] = ov[jj];
            }
        } else {
            #pragma unroll
            for (int j4 = 0; j4 < TN/4; j4++)
                *reinterpret_cast<float4*>(&C[(size_t)m*ldc + bn + tx*TN + j4*4]) =
                    *reinterpret_cast<const float4*>(&ov[j4*4]);
        }
    }
}

/* ---------------- causal depthwise conv + silu -------------------------- */
__global__ __launch_bounds__(256) void conv_silu_kernel(
    const float* __restrict__ xz, const float* __restrict__ cw,
    const float* __restrict__ cb, float* __restrict__ xc)
{
    int idx = blockIdx.x*blockDim.x + threadIdx.x;
    if (idx >= NROWS*DI) return;
    int d = idx % DI, r = idx / DI;
    int b = r / LL, l = r % LL;
    float acc = cb[d];
    #pragma unroll
    for (int j = 0; j < 4; j++) {
        int ls = l - 3 + j;
        if (ls >= 0)
            acc = fmaf(xz[(size_t)(b*LL + ls)*(2*DI) + d], cw[d*4 + j], acc);
    }
    float sig = 1.f / (1.f + expf(-acc));
    xc[idx] = acc * sig;
}

/* ---------------- scan pass 1: chunk-local scan ------------------------- */
__global__ __launch_bounds__(DI) void scan1_kernel(
    const float* __restrict__ dt, const float* __restrict__ xc,
    const float* __restrict__ dbl, const float* __restrict__ A_log,
    float* __restrict__ y, float* __restrict__ eend, float* __restrict__ S)
{
    int b = blockIdx.y, ck = blockIdx.x, d = threadIdx.x;
    __shared__ float sB[CL][DS], sC[CL][DS];
    for (int e = d; e < CL*DS; e += DI) {
        int l = e >> 4, n = e & 15;
        const float* row = dbl + (size_t)(b*LL + ck*CL + l)*44;
        sB[l][n] = row[12 + n];
        sC[l][n] = row[28 + n];
    }
    __syncthreads();
    float cn[DS], h[DS];
    const float* al = A_log + d*DS;
    #pragma unroll
    for (int n = 0; n < DS; n++) { cn[n] = -expf(al[n]) * LOG2E; h[n] = 0.f; }
    float Ss = 0.f;
    int base = (b*LL + ck*CL)*DI + d;
    for (int l = 0; l < CL; l++) {
        float dtv = dt[base + l*DI];
        float xcv = xc[base + l*DI];
        Ss += dtv;
        float u = dtv * xcv;
        float acc = 0.f;
        #pragma unroll
        for (int n = 0; n < DS; n++) {
            float e2 = exp2f(dtv * cn[n]);
            h[n] = fmaf(e2, h[n], u * sB[l][n]);
            acc = fmaf(h[n], sC[l][n], acc);
        }
        y[base + l*DI] = acc;
    }
    int si = (b*NC + ck)*DI + d;
    S[si] = Ss;
    #pragma unroll
    for (int n = 0; n < DS; n++) eend[(size_t)si*DS + n] = h[n];
}

/* ---------------- scan pass 2: inline carry + correction + gate --------- */
__global__ __launch_bounds__(DI) void scan3_kernel(
    const float* __restrict__ dt, const float* __restrict__ dbl,
    const float* __restrict__ A_log, const float* __restrict__ eend,
    const float* __restrict__ S,
    const float* __restrict__ xz, const float* __restrict__ xc,
    const float* __restrict__ Dsk, float* __restrict__ y)
{
    int b = blockIdx.y, ck = blockIdx.x, d = threadIdx.x;
    __shared__ float sC[CL][DS];
    for (int e = d; e < CL*DS; e += DI) {
        int l = e >> 4, n = e & 15;
        sC[l][n] = dbl[(size_t)(b*LL + ck*CL + l)*44 + 28 + n];
    }
    __syncthreads();
    float cn[DS], ci[DS];
    if (ck > 0) {
        const float* al = A_log + d*DS;
        #pragma unroll
        for (int n = 0; n < DS; n++) { cn[n] = -expf(al[n]) * LOG2E; ci[n] = 0.f; }
        for (int j = 0; j < ck; j++) {
            int si = (b*NC + j)*DI + d;
            float Sj = S[si];
            const float* ep = eend + (size_t)si*DS;
            #pragma unroll
            for (int n = 0; n < DS; n++)
                ci[n] = fmaf(exp2f(Sj * cn[n]), ci[n], ep[n]);
        }
    }
    float Dv = Dsk[d];
    int base = (b*LL + ck*CL)*DI + d;
    float tau = 0.f;
    for (int l = 0; l < CL; l++) {
        float dtv = dt[base + l*DI];
        tau += dtv;
        float yv = y[base + l*DI];
        if (ck > 0) {
            #pragma unroll
            for (int n = 0; n < DS; n++)
                yv = fmaf(exp2f(tau * cn[n]) * ci[n], sC[l][n], yv);
        }
        yv = fmaf(xc[base + l*DI], Dv, yv);
        int row = b*LL + ck*CL + l;
        float zv = xz[(size_t)row*(2*DI) + DI + d];
        yv *= zv / (1.f + expf(-zv));
        y[base + l*DI] = yv;
    }
}

/* ---------------- out_proj GEMM + fused add-residual + LayerNorm -------- */
/* BM=32, BN=192 (full row), BK=16, TM=4, TN=8, 192 threads, grid 160.     */
__global__ __launch_bounds__(192) void outproj_kernel(
    const float* __restrict__ A,          /* y, lda=384 */
    const float* __restrict__ W,          /* out_w layer: (192,384) */
    float* __restrict__ res,
    const float* __restrict__ lw, const float* __restrict__ lb,
    float* __restrict__ dst)
{
    constexpr int BMP = 36, BNP = 196, T = 24;
    __shared__ __align__(16) float As[2][16*BMP];
    __shared__ __align__(16) float Ws[2][16*BNP];
    __shared__ float sred[2][32][25];
    __shared__ float srow[32][2];

    int tid = threadIdx.x;
    int bm = blockIdx.x * 32;
    int tx = tid % 24, ty = tid / 24;

    ull acc[4][4];
    #pragma unroll
    for (int i = 0; i < 4; i++)
        #pragma unroll
        for (int j = 0; j < 4; j++) acc[i][j] = 0ull;

    float4 ar; float4 wr[4];

    #define OP_LOAD(k0)                                                       \
        if (tid < 128) {                                                      \
            int m = tid >> 2, kq = tid & 3;                                   \
            ar = *reinterpret_cast<const float4*>(                            \
                &A[(size_t)(bm + m)*DI + (k0) + kq*4]);                       \
        }                                                                     \
        _Pragma("unroll")                                                     \
        for (int i = 0; i < 4; i++) {                                         \
            int e = tid + i*192;                                              \
            int n = e >> 2, kq = e & 3;                                       \
            wr[i] = *reinterpret_cast<const float4*>(                         \
                &W[(size_t)n*DI + (k0) + kq*4]);                              \
        }

    #define OP_STORE(bf)                                                      \
        if (tid < 128) {                                                      \
            int m = tid >> 2, kq = tid & 3;                                   \
            As[bf][(kq*4+0)*BMP + m] = ar.x;                                  \
            As[bf][(kq*4+1)*BMP + m] = ar.y;                                  \
            As[bf][(kq*4+2)*BMP + m] = ar.z;                                  \
            As[bf][(kq*4+3)*BMP + m] = ar.w;                                  \
        }                                                                     \
        _Pragma("unroll")                                                     \
        for (int i = 0; i < 4; i++) {                                         \
            int e = tid + i*192;                                              \
            int n = e >> 2, kq = e & 3;                                       \
            Ws[bf][(kq*4+0)*BNP + n] = wr[i].x;                               \
            Ws[bf][(kq*4+1)*BNP + n] = wr[i].y;                               \
            Ws[bf][(kq*4+2)*BNP + n] = wr[i].z;                               \
            Ws[bf][(kq*4+3)*BNP + n] = wr[i].w;                               \
        }

    OP_LOAD(0)
    OP_STORE(0)
    __syncthreads();

    for (int t = 0; t < T; t++) {
        int buf = t & 1;
        if (t + 1 < T) { OP_LOAD((t+1)*16) }
        #pragma unroll
        for (int kk = 0; kk < 16; kk++) {
            float4 a4 = *reinterpret_cast<const float4*>(&As[buf][kk*BMP + ty*4]);
            float av[4] = {a4.x, a4.y, a4.z, a4.w};
            ull ad[4];
            #pragma unroll
            for (int i = 0; i < 4; i++) ad[i] = pack2(av[i]);
            ull bv[4];
            #pragma unroll
            for (int j = 0; j < 4; j++)
                bv[j] = *reinterpret_cast<const ull*>(&Ws[buf][kk*BNP + tx*8 + j*2]);
            #pragma unroll
            for (int i = 0; i < 4; i++)
                #pragma unroll
                for (int j = 0; j < 4; j++)
                    fma2(acc[i][j], ad[i], bv[j]);
        }
        if (t + 1 < T) { OP_STORE(buf ^ 1) }
        __syncthreads();
    }
    #undef OP_LOAD
    #undef OP_STORE

    /* epilogue: v = gemm + res; res = v; dst = LN(v) */
    float vr[4][8];
    #pragma unroll
    for (int i = 0; i < 4; i++) {
        int m = bm + ty*4 + i;
        float ov[8];
        #pragma unroll
        for (int j = 0; j < 4; j++) unpack2(acc[i][j], ov[2*j], ov[2*j+1]);
        float s = 0.f, q = 0.f;
        #pragma unroll
        for (int j = 0; j < 8; j++) {
            float v = ov[j] + res[(size_t)m*DM + tx*8 + j];
            vr[i][j] = v;
            s += v; q += v*v;
        }
        sred[0][ty*4 + i][tx] = s;
        sred[1][ty*4 + i][tx] = q;
    }
    __syncthreads();
    if (tid < 32) {
        float s = 0.f, q = 0.f;
        #pragma unroll
        for (int t = 0; t < 24; t++) { s += sred[0][tid][t]; q += sred[1][tid][t]; }
        float mean = s * (1.f/DM);
        float var  = q * (1.f/DM) - mean*mean;
        srow[tid][0] = mean;
        srow[tid][1] = rsqrtf(var + EPSLN);
    }
    __syncthreads();
    #pragma unroll
    for (int i = 0; i < 4; i++) {
        int rloc = ty*4 + i, m = bm + rloc;
        float mean = srow[rloc][0], rs = srow[rloc][1];
        #pragma unroll
        for (int j = 0; j < 8; j++) {
            int n = tx*8 + j;
            float v = vr[i][j];
            res[(size_t)m*DM + n] = v;
            dst[(size_t)m*DM + n] = (v - mean) * rs * lw[n] + lb[n];
        }
    }
}

/* ---------------- host driver ------------------------------------------- */
extern "C" void kernel_launch(void* const* d_in, const int* in_sizes, int n_in,
                              void* d_out, int out_size)
{
    const float* x_img   = (const float*)d_in[0];
    const float* z_img   = (const float*)d_in[1];
    const float* patch_w = (const float*)d_in[2];
    const float* patch_b = (const float*)d_in[3];
    const float* pos_x   = (const float*)d_in[4];
    const float* pos_z   = (const float*)d_in[5];
    const float* ln_w    = (const float*)d_in[6];
    const float* ln_b    = (const float*)d_in[7];
    const float* in_w    = (const float*)d_in[8];
    const float* conv_w  = (const float*)d_in[9];
    const float* conv_b  = (const float*)d_in[10];
    const float* xproj_w = (const float*)d_in[11];
    const float* dt_w    = (const float*)d_in[12];
    const float* dt_b    = (const float*)d_in[13];
    const float* A_log   = (const float*)d_in[14];
    const float* D_skip  = (const float*)d_in[15];
    const float* out_w   = (const float*)d_in[16];
    const float* fnorm_w = (const float*)d_in[17];
    const float* fnorm_b = (const float*)d_in[18];
    float* out = (float*)d_out;

    float *hidden, *res, *hn, *xz, *xc, *dbl, *dt, *y, *eend, *S;
    cudaGetSymbolAddress((void**)&hidden, g_hidden);
    cudaGetSymbolAddress((void**)&res,    g_res);
    cudaGetSymbolAddress((void**)&hn,     g_hn);
    cudaGetSymbolAddress((void**)&xz,     g_xz);
    cudaGetSymbolAddress((void**)&xc,     g_xc);
    cudaGetSymbolAddress((void**)&dbl,    g_dbl);
    cudaGetSymbolAddress((void**)&dt,     g_dt);
    cudaGetSymbolAddress((void**)&y,      g_y);
    cudaGetSymbolAddress((void**)&eend,   g_eend);
    cudaGetSymbolAddress((void**)&S,      g_S);

    patch_kernel<<<NROWS/4, 192>>>(x_img, z_img, patch_w, patch_b,
                                   pos_x, pos_z, hidden, res);
    addnorm_kernel<<<NROWS, 192>>>(hidden, res, ln_w, ln_b, hn, 1);

    for (int l = 0; l < DEPTH; l++) {
        /* in_proj: (5120,192) @ (768,192)^T -> xz (5120,768) */
        gemm2_kernel<64,128,16,8,8,192,0,false><<<dim3(6, 80), 128>>>(
            hn, DM, in_w + (size_t)l*2*DI*DM, xz, 2*DI, 2*DI, nullptr);

        conv_silu_kernel<<<(NROWS*DI + 255)/256, 256>>>(xz, conv_w + l*DI*4,
                                                        conv_b + l*DI, xc);

        /* x_proj: (5120,384) @ (44,384)^T -> dbl (5120,44) */
        gemm2_kernel<64,64,16,4,8,384,0,true><<<dim3(1, 80), 128>>>(
            xc, DI, xproj_w + (size_t)l*44*DI, dbl, 44, 44, nullptr);

        /* dt_proj + bias + softplus: (5120,12) @ (384,12)^T -> dt (5120,384) */
        gemm2_kernel<64,64,12,4,8,12,1,false><<<dim3(6, 80), 128>>>(
            dbl, 44, dt_w + (size_t)l*DI*DR, dt, DI, DI, dt_b + l*DI);

        scan1_kernel<<<dim3(NC, BB), DI>>>(dt, xc, dbl, A_log + (size_t)l*DI*DS,
                                           y, eend, S);
        scan3_kernel<<<dim3(NC, BB), DI>>>(dt, dbl, A_log + (size_t)l*DI*DS,
                                           eend, S, xz, xc, D_skip + l*DI, y);

        /* out_proj + residual add + next-layer LN (fnorm on last layer) */
        const float* lw = (l < DEPTH-1) ? ln_w + (l+1)*DM : fnorm_w;
        const float* lb = (l < DEPTH-1) ? ln_b + (l+1)*DM : fnorm_b;
        float* dst = (l < DEPTH-1) ? hn : out;
        outproj_kernel<<<NROWS/32, 192>>>(y, out_w + (size_t)l*DM*DI,
                                          res, lw, lb, dst);
    }
}

// round 8
// speedup vs baseline: 1.1724x; 1.0096x over previous
#include <cuda_runtime.h>
#include <math.h>

#define BB 16
#define LL 320
#define DM 192
#define DI 384
#define DS 16
#define DR 12
#define DEPTH 24
#define NROWS (BB*LL)      /* 5120 */
#define NC 10
#define CL 32
#define LOG2E 1.4426950408889634f
#define EPSLN 1e-5f

typedef unsigned long long ull;

/* ---------------- scratch (static device globals; no allocation) -------- */
__device__ float g_hidden[NROWS*DM];
__device__ float g_res[NROWS*DM];
__device__ float g_hn[NROWS*DM];
__device__ float g_xz[NROWS*2*DI];
__device__ float g_xc[NROWS*DI];
__device__ float g_dbl[NROWS*44];
__device__ float g_dt[NROWS*DI];
__device__ float g_y[NROWS*DI];
__device__ float g_eend[BB*NC*DI*DS];
__device__ float g_S[BB*NC*DI];
__device__ float g_cin[BB*NC*DI*DS];

__device__ __forceinline__ void fma2(ull &d, ull a, ull b) {
    asm("fma.rn.f32x2 %0, %1, %2, %3;" : "=l"(d) : "l"(a), "l"(b), "l"(d));
}
__device__ __forceinline__ ull pack2(float v) {
    ull d;
    asm("mov.b64 %0, {%1, %1};" : "=l"(d) : "f"(v));
    return d;
}
__device__ __forceinline__ void unpack2(ull v, float &lo, float &hi) {
    asm("mov.b64 {%0, %1}, %2;" : "=f"(lo), "=f"(hi) : "l"(v));
}

/* ---------------- patch embed + pos, zero residual ---------------------- */
__global__ __launch_bounds__(192) void patch_kernel(
    const float* __restrict__ ximg, const float* __restrict__ zimg,
    const float* __restrict__ pw, const float* __restrict__ pb,
    const float* __restrict__ posx, const float* __restrict__ posz,
    float* __restrict__ hidden, float* __restrict__ res)
{
    __shared__ float sp[4][768];
    int tg = blockIdx.x, tid = threadIdx.x;
    for (int i = 0; i < 4; i++) {
        int r = tg*4 + i, b = r / LL, t = r % LL;
        for (int c = tid; c < 768; c += 192) {
            int ch = c >> 8, p = c & 255, py = p >> 4, px = p & 15;
            float v;
            if (t < 64) {
                int ph = (t >> 3)*16 + py, pwi = (t & 7)*16 + px;
                v = zimg[((b*3 + ch)*128 + ph)*128 + pwi];
            } else {
                int tx = t - 64;
                int ph = (tx >> 4)*16 + py, pwi = (tx & 15)*16 + px;
                v = ximg[((b*3 + ch)*256 + ph)*256 + pwi];
            }
            sp[i][c] = v;
        }
    }
    __syncthreads();
    int d = tid;
    float a0 = 0.f, a1 = 0.f, a2 = 0.f, a3 = 0.f;
    const float* wr = pw + d*768;
    for (int c = 0; c < 768; c++) {
        float w = wr[c];
        a0 = fmaf(w, sp[0][c], a0);
        a1 = fmaf(w, sp[1][c], a1);
        a2 = fmaf(w, sp[2][c], a2);
        a3 = fmaf(w, sp[3][c], a3);
    }
    float accs[4] = {a0, a1, a2, a3};
    for (int i = 0; i < 4; i++) {
        int r = tg*4 + i, t = r % LL;
        float pos = (t < 64) ? posz[t*DM + d] : posx[(t - 64)*DM + d];
        hidden[r*DM + d] = accs[i] + pb[d] + pos;
        res[r*DM + d] = 0.f;
    }
}

/* ---------------- fused add + layernorm --------------------------------- */
__global__ __launch_bounds__(192) void addnorm_kernel(
    const float* __restrict__ hid, float* __restrict__ res,
    const float* __restrict__ w, const float* __restrict__ b,
    float* __restrict__ o, int write_res)
{
    int row = blockIdx.x, d = threadIdx.x;
    float v = hid[row*DM + d] + res[row*DM + d];
    if (write_res) res[row*DM + d] = v;
    float s = v, sq = v*v;
    #pragma unroll
    for (int off = 16; off > 0; off >>= 1) {
        s  += __shfl_down_sync(0xffffffffu, s,  off);
        sq += __shfl_down_sync(0xffffffffu, sq, off);
    }
    __shared__ float sh1[6], sh2[6];
    int wid = d >> 5, lane = d & 31;
    if (lane == 0) { sh1[wid] = s; sh2[wid] = sq; }
    __syncthreads();
    float ts = 0.f, tq = 0.f;
    #pragma unroll
    for (int i = 0; i < 6; i++) { ts += sh1[i]; tq += sh2[i]; }
    float mean = ts * (1.f/DM);
    float var  = tq * (1.f/DM) - mean*mean;
    float rs = rsqrtf(var + EPSLN);
    o[row*DM + d] = (v - mean) * rs * w[d] + b[d];
}

/* ---------------- f32x2 packed GEMM: C[M,N] = A[M,K] @ W[N,K]^T ---------- */
template<int BM, int BN, int BK, int TM, int TN, int KT, int EP, bool NG>
__global__ __launch_bounds__((BM/TM)*(BN/TN)) void gemm2_kernel(
    const float* __restrict__ A, int lda,
    const float* __restrict__ W,
    float* __restrict__ C, int ldc,
    int N, const float* __restrict__ bias)
{
    constexpr int NT  = (BM/TM)*(BN/TN);
    constexpr int BK4 = BK/4;
    constexpr int NA  = (BM*BK4 + NT - 1)/NT;
    constexpr int NW  = (BN*BK4 + NT - 1)/NT;
    constexpr int BMP = BM + 4, BNP = BN + 4;
    constexpr int T   = KT/BK;

    __shared__ __align__(16) float As[2][BK*BMP];
    __shared__ __align__(16) float Ws[2][BK*BNP];

    int tid = threadIdx.x;
    int bn = blockIdx.x * BN, bm = blockIdx.y * BM;
    int tx = tid % (BN/TN), ty = tid / (BN/TN);

    ull acc[TM][TN/2];
    #pragma unroll
    for (int i = 0; i < TM; i++)
        #pragma unroll
        for (int j = 0; j < TN/2; j++) acc[i][j] = 0ull;

    float4 ar[NA], wr[NW];

    #define LOAD_TILE(k0)                                                     \
        _Pragma("unroll")                                                     \
        for (int i = 0; i < NA; i++) {                                        \
            int e = tid + i*NT;                                               \
            if ((BM*BK4) % NT == 0 || e < BM*BK4) {                           \
                int m = e / BK4, kq = e % BK4;                                \
                ar[i] = *reinterpret_cast<const float4*>(                     \
                    &A[(size_t)(bm + m)*lda + (k0) + kq*4]);                  \
            }                                                                 \
        }                                                                     \
        _Pragma("unroll")                                                     \
        for (int i = 0; i < NW; i++) {                                        \
            int e = tid + i*NT;                                               \
            if ((BN*BK4) % NT == 0 || e < BN*BK4) {                           \
                int nn = e / BK4, kq = e % BK4;                               \
                if (NG && bn + nn >= N) wr[i] = make_float4(0.f,0.f,0.f,0.f); \
                else wr[i] = *reinterpret_cast<const float4*>(                \
                    &W[(size_t)(bn + nn)*KT + (k0) + kq*4]);                  \
            }                                                                 \
        }

    #define STORE_TILE(bf)                                                    \
        _Pragma("unroll")                                                     \
        for (int i = 0; i < NA; i++) {                                        \
            int e = tid + i*NT;                                               \
            if ((BM*BK4) % NT == 0 || e < BM*BK4) {                           \
                int m = e / BK4, kq = e % BK4;                                \
                As[bf][(kq*4+0)*BMP + m] = ar[i].x;                           \
                As[bf][(kq*4+1)*BMP + m] = ar[i].y;                           \
                As[bf][(kq*4+2)*BMP + m] = ar[i].z;                           \
                As[bf][(kq*4+3)*BMP + m] = ar[i].w;                           \
            }                                                                 \
        }                                                                     \
        _Pragma("unroll")                                                     \
        for (int i = 0; i < NW; i++) {                                        \
            int e = tid + i*NT;                                               \
            if ((BN*BK4) % NT == 0 || e < BN*BK4) {                           \
                int nn = e / BK4, kq = e % BK4;                               \
                Ws[bf][(kq*4+0)*BNP + nn] = wr[i].x;                          \
                Ws[bf][(kq*4+1)*BNP + nn] = wr[i].y;                          \
                Ws[bf][(kq*4+2)*BNP + nn] = wr[i].z;                          \
                Ws[bf][(kq*4+3)*BNP + nn] = wr[i].w;                          \
            }                                                                 \
        }

    LOAD_TILE(0)
    STORE_TILE(0)
    __syncthreads();

    for (int t = 0; t < T; t++) {
        int buf = t & 1;
        if (t + 1 < T) { LOAD_TILE((t+1)*BK) }
        #pragma unroll
        for (int kk = 0; kk < BK; kk++) {
            float av[TM];
            #pragma unroll
            for (int i4 = 0; i4 < TM/4; i4++)
                *reinterpret_cast<float4*>(&av[i4*4]) =
                    *reinterpret_cast<const float4*>(&As[buf][kk*BMP + ty*TM + i4*4]);
            ull ad[TM];
            #pragma unroll
            for (int i = 0; i < TM; i++) ad[i] = pack2(av[i]);
            ull bv[TN/2];
            #pragma unroll
            for (int j = 0; j < TN/2; j++)
                bv[j] = *reinterpret_cast<const ull*>(&Ws[buf][kk*BNP + tx*TN + j*2]);
            #pragma unroll
            for (int i = 0; i < TM; i++)
                #pragma unroll
                for (int j = 0; j < TN/2; j++)
                    fma2(acc[i][j], ad[i], bv[j]);
        }
        if (t + 1 < T) { STORE_TILE(buf ^ 1) }
        __syncthreads();
    }
    #undef LOAD_TILE
    #undef STORE_TILE

    #pragma unroll
    for (int i = 0; i < TM; i++) {
        int m = bm + ty*TM + i;
        float ov[TN];
        #pragma unroll
        for (int j = 0; j < TN/2; j++) unpack2(acc[i][j], ov[2*j], ov[2*j+1]);
        if (EP == 1) {
            #pragma unroll
            for (int jj = 0; jj < TN; jj++) {
                int n = bn + tx*TN + jj;
                float v = ov[jj] + bias[n];
                ov[jj] = (v > 20.f) ? v : log1pf(expf(v));
            }
        }
        if (NG) {
            #pragma unroll
            for (int jj = 0; jj < TN; jj++) {
                int n = bn + tx*TN + jj;
                if (n < N) C[(size_t)m*ldc + n] = ov[jj];
            }
        } else {
            #pragma unroll
            for (int j4 = 0; j4 < TN/4; j4++)
                *reinterpret_cast<float4*>(&C[(size_t)m*ldc + bn + tx*TN + j4*4]) =
                    *reinterpret_cast<const float4*>(&ov[j4*4]);
        }
    }
}

/* ------- fused conv+silu (A producer) -> x_proj GEMM -> dt_proj --------- */
/* BM=32 rows/block (grid 160), BN=64 (covers N=44), BK=16, 128 threads.   */
/* A tile = silu(conv(xz)) computed on the fly; xc written as side effect. */
__global__ __launch_bounds__(128) void projx_kernel(
    const float* __restrict__ xz, const float* __restrict__ cw,
    const float* __restrict__ cb, const float* __restrict__ xw,
    const float* __restrict__ dtw, const float* __restrict__ dtb,
    float* __restrict__ xc_g, float* __restrict__ dbl_g,
    float* __restrict__ dt_g)
{
    constexpr int BMP = 36, BNP = 68, T = 24;
    __shared__ __align__(16) float As[2][16*BMP];
    __shared__ __align__(16) float Ws[2][16*BNP];
    __shared__ float dtw_s[DI*13];
    __shared__ float dtb_s[DI];
    __shared__ float cw_s[DI*4];
    __shared__ float cb_s[DI];
    __shared__ float dbl_s[32*13];

    int tid = threadIdx.x;
    int r0 = blockIdx.x * 32;
    int b = r0 / LL, l0 = r0 % LL;

    for (int e = tid; e < DI*DR; e += 128)
        dtw_s[(e/DR)*13 + (e%DR)] = dtw[e];
    for (int e = tid; e < DI*4; e += 128) cw_s[e] = cw[e];
    for (int e = tid; e < DI; e += 128) { cb_s[e] = cb[e]; dtb_s[e] = dtb[e]; }
    __syncthreads();

    float av[4]; float4 wr[2];

    /* conv+silu A producer: 32x16 elements, 4/thread */
    #define PJ_LOADA(k0)                                                      \
        _Pragma("unroll")                                                     \
        for (int i = 0; i < 4; i++) {                                         \
            int e = tid + i*128;                                              \
            int m = e >> 4, k = e & 15;                                       \
            int d = (k0) + k;                                                 \
            int l = l0 + m;                                                   \
            float a = cb_s[d];                                                \
            _Pragma("unroll")                                                 \
            for (int j = 0; j < 4; j++) {                                     \
                int ls = l - 3 + j;                                           \
                if (ls >= 0)                                                  \
                    a = fmaf(xz[(size_t)(b*LL + ls)*(2*DI) + d],              \
                             cw_s[d*4 + j], a);                               \
            }                                                                 \
            a = a / (1.f + expf(-a));                                         \
            av[i] = a;                                                        \
            xc_g[(size_t)(r0 + m)*DI + d] = a;                                \
        }

    #define PJ_LOADW(k0)                                                      \
        _Pragma("unroll")                                                     \
        for (int i = 0; i < 2; i++) {                                         \
            int e = tid + i*128;                                              \
            int nn = e >> 2, kq = e & 3;                                      \
            if (nn < 44)                                                      \
                wr[i] = *reinterpret_cast<const float4*>(                     \
                    &xw[(size_t)nn*DI + (k0) + kq*4]);                        \
            else wr[i] = make_float4(0.f, 0.f, 0.f, 0.f);                     \
        }

    #define PJ_STORE(bf)                                                      \
        _Pragma("unroll")                                                     \
        for (int i = 0; i < 4; i++) {                                         \
            int e = tid + i*128;                                              \
            int m = e >> 4, k = e & 15;                                       \
            As[bf][k*BMP + m] = av[i];                                        \
        }                                                                     \
        _Pragma("unroll")                                                     \
        for (int i = 0; i < 2; i++) {                                         \
            int e = tid + i*128;                                              \
            int nn = e >> 2, kq = e & 3;                                      \
            Ws[bf][(kq*4+0)*BNP + nn] = wr[i].x;                              \
            Ws[bf][(kq*4+1)*BNP + nn] = wr[i].y;                              \
            Ws[bf][(kq*4+2)*BNP + nn] = wr[i].z;                              \
            Ws[bf][(kq*4+3)*BNP + nn] = wr[i].w;                              \
        }

    PJ_LOADA(0)
    PJ_LOADW(0)
    PJ_STORE(0)
    __syncthreads();

    /* main x_proj loop: TM=2, TN=8 -> (32/2)*(64/8)=128 threads */
    int tx = tid & 7, ty = tid >> 3;
    ull acc[2][4];
    #pragma unroll
    for (int i = 0; i < 2; i++)
        #pragma unroll
        for (int j = 0; j < 4; j++) acc[i][j] = 0ull;

    for (int t = 0; t < T; t++) {
        int buf = t & 1;
        if (t + 1 < T) { PJ_LOADA((t+1)*16) PJ_LOADW((t+1)*16) }
        #pragma unroll
        for (int kk = 0; kk < 16; kk++) {
            ull ad[2];
            ad[0] = pack2(As[buf][kk*BMP + ty*2 + 0]);
            ad[1] = pack2(As[buf][kk*BMP + ty*2 + 1]);
            ull bv[4];
            #pragma unroll
            for (int j = 0; j < 4; j++)
                bv[j] = *reinterpret_cast<const ull*>(&Ws[buf][kk*BNP + tx*8 + j*2]);
            #pragma unroll
            for (int i = 0; i < 2; i++)
                #pragma unroll
                for (int j = 0; j < 4; j++)
                    fma2(acc[i][j], ad[i], bv[j]);
        }
        if (t + 1 < T) { PJ_STORE(buf ^ 1) }
        __syncthreads();
    }
    #undef PJ_LOADA
    #undef PJ_LOADW
    #undef PJ_STORE

    /* epilogue: write dbl (n<44) to global; n<12 also to smem for dt phase */
    #pragma unroll
    for (int i = 0; i < 2; i++) {
        int m = ty*2 + i;
        float ov[8];
        #pragma unroll
        for (int j = 0; j < 4; j++) unpack2(acc[i][j], ov[2*j], ov[2*j+1]);
        #pragma unroll
        for (int jj = 0; jj < 8; jj++) {
            int n = tx*8 + jj;
            if (n < 44) dbl_g[(size_t)(r0 + m)*44 + n] = ov[jj];
            if (n < 12) dbl_s[m*13 + n] = ov[jj];
        }
    }
    __syncthreads();

    /* dt_proj + bias + softplus: 32x384 outputs, K=12 from smem */
    #pragma unroll 4
    for (int e = tid; e < 32*DI; e += 128) {
        int m = e / DI, n = e % DI;
        float a = dtb_s[n];
        #pragma unroll
        for (int k = 0; k < 12; k++)
            a = fmaf(dbl_s[m*13 + k], dtw_s[n*13 + k], a);
        a = (a > 20.f) ? a : log1pf(expf(a));
        dt_g[(size_t)(r0 + m)*DI + n] = a;
    }
}

/* ---------------- scan pass 1: chunk-local scan ------------------------- */
__global__ __launch_bounds__(DI) void scan1_kernel(
    const float* __restrict__ dt, const float* __restrict__ xc,
    const float* __restrict__ dbl, const float* __restrict__ A_log,
    float* __restrict__ y, float* __restrict__ eend, float* __restrict__ S)
{
    int b = blockIdx.y, ck = blockIdx.x, d = threadIdx.x;
    __shared__ float sB[CL][DS], sC[CL][DS];
    for (int e = d; e < CL*DS; e += DI) {
        int l = e >> 4, n = e & 15;
        const float* row = dbl + (size_t)(b*LL + ck*CL + l)*44;
        sB[l][n] = row[12 + n];
        sC[l][n] = row[28 + n];
    }
    __syncthreads();
    float cn[DS], h[DS];
    const float* al = A_log + d*DS;
    #pragma unroll
    for (int n = 0; n < DS; n++) { cn[n] = -expf(al[n]) * LOG2E; h[n] = 0.f; }
    float Ss = 0.f;
    int base = (b*LL + ck*CL)*DI + d;
    for (int l = 0; l < CL; l++) {
        float dtv = dt[base + l*DI];
        float xcv = xc[base + l*DI];
        Ss += dtv;
        float u = dtv * xcv;
        float acc = 0.f;
        #pragma unroll
        for (int n = 0; n < DS; n++) {
            float e2 = exp2f(dtv * cn[n]);
            h[n] = fmaf(e2, h[n], u * sB[l][n]);
            acc = fmaf(h[n], sC[l][n], acc);
        }
        y[base + l*DI] = acc;
    }
    int si = (b*NC + ck)*DI + d;
    S[si] = Ss;
    #pragma unroll
    for (int n = 0; n < DS; n++) eend[(size_t)si*DS + n] = h[n];
}

/* ---------------- carry propagation across chunks ----------------------- */
__global__ __launch_bounds__(256) void carry_kernel(
    const float* __restrict__ eend, const float* __restrict__ S,
    const float* __restrict__ A_log, float* __restrict__ cin)
{
    int idx = blockIdx.x*blockDim.x + threadIdx.x;
    if (idx >= BB*DI*DS) return;
    int n = idx & 15, d = (idx >> 4) % DI, b = idx / (DI*DS);
    float cf = -expf(A_log[d*DS + n]) * LOG2E;
    float c = 0.f;
    for (int k = 0; k < NC; k++) {
        int si = (b*NC + k)*DI + d;
        cin[(size_t)si*DS + n] = c;
        c = fmaf(exp2f(S[si] * cf), c, eend[(size_t)si*DS + n]);
    }
}

/* ---------------- scan pass 3: carry correction + D skip + z gate ------- */
__global__ __launch_bounds__(DI) void scan3_kernel(
    const float* __restrict__ dt, const float* __restrict__ dbl,
    const float* __restrict__ A_log, const float* __restrict__ cin,
    const float* __restrict__ xz, const float* __restrict__ xc,
    const float* __restrict__ Dsk, float* __restrict__ y)
{
    int b = blockIdx.y, ck = blockIdx.x, d = threadIdx.x;
    __shared__ float sC[CL][DS];
    for (int e = d; e < CL*DS; e += DI) {
        int l = e >> 4, n = e & 15;
        sC[l][n] = dbl[(size_t)(b*LL + ck*CL + l)*44 + 28 + n];
    }
    __syncthreads();
    float cn[DS], ci[DS];
    if (ck > 0) {
        const float* al = A_log + d*DS;
        const float* cp = cin + (size_t)((b*NC + ck)*DI + d)*DS;
        #pragma unroll
        for (int n = 0; n < DS; n++) { cn[n] = -expf(al[n]) * LOG2E; ci[n] = cp[n]; }
    }
    float Dv = Dsk[d];
    int base = (b*LL + ck*CL)*DI + d;
    float tau = 0.f;
    for (int l = 0; l < CL; l++) {
        float dtv = dt[base + l*DI];
        tau += dtv;
        float yv = y[base + l*DI];
        if (ck > 0) {
            #pragma unroll
            for (int n = 0; n < DS; n++)
                yv = fmaf(exp2f(tau * cn[n]) * ci[n], sC[l][n], yv);
        }
        yv = fmaf(xc[base + l*DI], Dv, yv);
        int row = b*LL + ck*CL + l;
        float zv = xz[(size_t)row*(2*DI) + DI + d];
        yv *= zv / (1.f + expf(-zv));
        y[base + l*DI] = yv;
    }
}

/* ---------------- host driver ------------------------------------------- */
extern "C" void kernel_launch(void* const* d_in, const int* in_sizes, int n_in,
                              void* d_out, int out_size)
{
    const float* x_img   = (const float*)d_in[0];
    const float* z_img   = (const float*)d_in[1];
    const float* patch_w = (const float*)d_in[2];
    const float* patch_b = (const float*)d_in[3];
    const float* pos_x   = (const float*)d_in[4];
    const float* pos_z   = (const float*)d_in[5];
    const float* ln_w    = (const float*)d_in[6];
    const float* ln_b    = (const float*)d_in[7];
    const float* in_w    = (const float*)d_in[8];
    const float* conv_w  = (const float*)d_in[9];
    const float* conv_b  = (const float*)d_in[10];
    const float* xproj_w = (const float*)d_in[11];
    const float* dt_w    = (const float*)d_in[12];
    const float* dt_b    = (const float*)d_in[13];
    const float* A_log   = (const float*)d_in[14];
    const float* D_skip  = (const float*)d_in[15];
    const float* out_w   = (const float*)d_in[16];
    const float* fnorm_w = (const float*)d_in[17];
    const float* fnorm_b = (const float*)d_in[18];
    float* out = (float*)d_out;

    float *hidden, *res, *hn, *xz, *xc, *dbl, *dt, *y, *eend, *S, *cin;
    cudaGetSymbolAddress((void**)&hidden, g_hidden);
    cudaGetSymbolAddress((void**)&res,    g_res);
    cudaGetSymbolAddress((void**)&hn,     g_hn);
    cudaGetSymbolAddress((void**)&xz,     g_xz);
    cudaGetSymbolAddress((void**)&xc,     g_xc);
    cudaGetSymbolAddress((void**)&dbl,    g_dbl);
    cudaGetSymbolAddress((void**)&dt,     g_dt);
    cudaGetSymbolAddress((void**)&y,      g_y);
    cudaGetSymbolAddress((void**)&eend,   g_eend);
    cudaGetSymbolAddress((void**)&S,      g_S);
    cudaGetSymbolAddress((void**)&cin,    g_cin);

    patch_kernel<<<NROWS/4, 192>>>(x_img, z_img, patch_w, patch_b,
                                   pos_x, pos_z, hidden, res);

    for (int l = 0; l < DEPTH; l++) {
        addnorm_kernel<<<NROWS, 192>>>(hidden, res, ln_w + l*DM, ln_b + l*DM, hn, 1);

        /* in_proj: (5120,192) @ (768,192)^T -> xz (5120,768) */
        gemm2_kernel<64,128,16,8,8,192,0,false><<<dim3(6, 80), 128>>>(
            hn, DM, in_w + (size_t)l*2*DI*DM, xz, 2*DI, 2*DI, nullptr);

        /* fused conv+silu -> x_proj -> dt_proj(+softplus) */
        projx_kernel<<<NROWS/32, 128>>>(
            xz, conv_w + l*DI*4, conv_b + l*DI,
            xproj_w + (size_t)l*44*DI, dt_w + (size_t)l*DI*DR, dt_b + l*DI,
            xc, dbl, dt);

        scan1_kernel<<<dim3(NC, BB), DI>>>(dt, xc, dbl, A_log + (size_t)l*DI*DS,
                                           y, eend, S);
        carry_kernel<<<(BB*DI*DS + 255)/256, 256>>>(eend, S,
                                                    A_log + (size_t)l*DI*DS, cin);
        scan3_kernel<<<dim3(NC, BB), DI>>>(dt, dbl, A_log + (size_t)l*DI*DS,
                                           cin, xz, xc, D_skip + l*DI, y);

        /* out_proj: (5120,384) @ (192,384)^T -> hidden (5120,192) */
        gemm2_kernel<64,64,16,4,8,384,0,false><<<dim3(3, 80), 128>>>(
            y, DI, out_w + (size_t)l*DM*DI, hidden, DM, DM, nullptr);
    }

    addnorm_kernel<<<NROWS, 192>>>(hidden, res, fnorm_w, fnorm_b, out, 0);
}

// round 9
// speedup vs baseline: 1.3330x; 1.1370x over previous
#include <cuda_runtime.h>
#include <math.h>

#define BB 16
#define LL 320
#define DM 192
#define DI 384
#define DS 16
#define DR 12
#define DEPTH 24
#define NROWS (BB*LL)      /* 5120 */
#define NC 10
#define CL 32
#define LOG2E 1.4426950408889634f
#define EPSLN 1e-5f

typedef unsigned long long ull;

/* ---------------- scratch (static device globals; no allocation) -------- */
__device__ float g_hidden[NROWS*DM];
__device__ float g_res[NROWS*DM];
__device__ float g_hn[NROWS*DM];
__device__ float g_xz[NROWS*2*DI];
__device__ float g_xc[NROWS*DI];
__device__ float g_dbl[NROWS*44];
__device__ float g_y[NROWS*DI];
__device__ float g_eend[BB*NC*DI*DS];
__device__ float g_S[BB*NC*DI];
__device__ float g_cin[BB*NC*DI*DS];

__device__ __forceinline__ void fma2(ull &d, ull a, ull b) {
    asm("fma.rn.f32x2 %0, %1, %2, %3;" : "=l"(d) : "l"(a), "l"(b), "l"(d));
}
__device__ __forceinline__ ull pack2(float v) {
    ull d;
    asm("mov.b64 %0, {%1, %1};" : "=l"(d) : "f"(v));
    return d;
}
__device__ __forceinline__ void unpack2(ull v, float &lo, float &hi) {
    asm("mov.b64 {%0, %1}, %2;" : "=f"(lo), "=f"(hi) : "l"(v));
}

/* ---------------- patch embed + pos, zero residual ---------------------- */
__global__ __launch_bounds__(192) void patch_kernel(
    const float* __restrict__ ximg, const float* __restrict__ zimg,
    const float* __restrict__ pw, const float* __restrict__ pb,
    const float* __restrict__ posx, const float* __restrict__ posz,
    float* __restrict__ hidden, float* __restrict__ res)
{
    __shared__ float sp[4][768];
    int tg = blockIdx.x, tid = threadIdx.x;
    for (int i = 0; i < 4; i++) {
        int r = tg*4 + i, b = r / LL, t = r % LL;
        for (int c = tid; c < 768; c += 192) {
            int ch = c >> 8, p = c & 255, py = p >> 4, px = p & 15;
            float v;
            if (t < 64) {
                int ph = (t >> 3)*16 + py, pwi = (t & 7)*16 + px;
                v = zimg[((b*3 + ch)*128 + ph)*128 + pwi];
            } else {
                int tx = t - 64;
                int ph = (tx >> 4)*16 + py, pwi = (tx & 15)*16 + px;
                v = ximg[((b*3 + ch)*256 + ph)*256 + pwi];
            }
            sp[i][c] = v;
        }
    }
    __syncthreads();
    int d = tid;
    float a0 = 0.f, a1 = 0.f, a2 = 0.f, a3 = 0.f;
    const float* wr = pw + d*768;
    for (int c = 0; c < 768; c++) {
        float w = wr[c];
        a0 = fmaf(w, sp[0][c], a0);
        a1 = fmaf(w, sp[1][c], a1);
        a2 = fmaf(w, sp[2][c], a2);
        a3 = fmaf(w, sp[3][c], a3);
    }
    float accs[4] = {a0, a1, a2, a3};
    for (int i = 0; i < 4; i++) {
        int r = tg*4 + i, t = r % LL;
        float pos = (t < 64) ? posz[t*DM + d] : posx[(t - 64)*DM + d];
        hidden[r*DM + d] = accs[i] + pb[d] + pos;
        res[r*DM + d] = 0.f;
    }
}

/* ---------------- fused add + layernorm --------------------------------- */
__global__ __launch_bounds__(192) void addnorm_kernel(
    const float* __restrict__ hid, float* __restrict__ res,
    const float* __restrict__ w, const float* __restrict__ b,
    float* __restrict__ o, int write_res)
{
    int row = blockIdx.x, d = threadIdx.x;
    float v = hid[row*DM + d] + res[row*DM + d];
    if (write_res) res[row*DM + d] = v;
    float s = v, sq = v*v;
    #pragma unroll
    for (int off = 16; off > 0; off >>= 1) {
        s  += __shfl_down_sync(0xffffffffu, s,  off);
        sq += __shfl_down_sync(0xffffffffu, sq, off);
    }
    __shared__ float sh1[6], sh2[6];
    int wid = d >> 5, lane = d & 31;
    if (lane == 0) { sh1[wid] = s; sh2[wid] = sq; }
    __syncthreads();
    float ts = 0.f, tq = 0.f;
    #pragma unroll
    for (int i = 0; i < 6; i++) { ts += sh1[i]; tq += sh2[i]; }
    float mean = ts * (1.f/DM);
    float var  = tq * (1.f/DM) - mean*mean;
    float rs = rsqrtf(var + EPSLN);
    o[row*DM + d] = (v - mean) * rs * w[d] + b[d];
}

/* ---------------- f32x2 packed GEMM: C[M,N] = A[M,K] @ W[N,K]^T ---------- */
template<int BM, int BN, int BK, int TM, int TN, int KT, int EP, bool NG>
__global__ __launch_bounds__((BM/TM)*(BN/TN)) void gemm2_kernel(
    const float* __restrict__ A, int lda,
    const float* __restrict__ W,
    float* __restrict__ C, int ldc,
    int N, const float* __restrict__ bias)
{
    constexpr int NT  = (BM/TM)*(BN/TN);
    constexpr int BK4 = BK/4;
    constexpr int NA  = (BM*BK4 + NT - 1)/NT;
    constexpr int NW  = (BN*BK4 + NT - 1)/NT;
    constexpr int BMP = BM + 4, BNP = BN + 4;
    constexpr int T   = KT/BK;

    __shared__ __align__(16) float As[2][BK*BMP];
    __shared__ __align__(16) float Ws[2][BK*BNP];

    int tid = threadIdx.x;
    int bn = blockIdx.x * BN, bm = blockIdx.y * BM;
    int tx = tid % (BN/TN), ty = tid / (BN/TN);

    ull acc[TM][TN/2];
    #pragma unroll
    for (int i = 0; i < TM; i++)
        #pragma unroll
        for (int j = 0; j < TN/2; j++) acc[i][j] = 0ull;

    float4 ar[NA], wr[NW];

    #define LOAD_TILE(k0)                                                     \
        _Pragma("unroll")                                                     \
        for (int i = 0; i < NA; i++) {                                        \
            int e = tid + i*NT;                                               \
            if ((BM*BK4) % NT == 0 || e < BM*BK4) {                           \
                int m = e / BK4, kq = e % BK4;                                \
                ar[i] = *reinterpret_cast<const float4*>(                     \
                    &A[(size_t)(bm + m)*lda + (k0) + kq*4]);                  \
            }                                                                 \
        }                                                                     \
        _Pragma("unroll")                                                     \
        for (int i = 0; i < NW; i++) {                                        \
            int e = tid + i*NT;                                               \
            if ((BN*BK4) % NT == 0 || e < BN*BK4) {                           \
                int nn = e / BK4, kq = e % BK4;                               \
                if (NG && bn + nn >= N) wr[i] = make_float4(0.f,0.f,0.f,0.f); \
                else wr[i] = *reinterpret_cast<const float4*>(                \
                    &W[(size_t)(bn + nn)*KT + (k0) + kq*4]);                  \
            }                                                                 \
        }

    #define STORE_TILE(bf)                                                    \
        _Pragma("unroll")                                                     \
        for (int i = 0; i < NA; i++) {                                        \
            int e = tid + i*NT;                                               \
            if ((BM*BK4) % NT == 0 || e < BM*BK4) {                           \
                int m = e / BK4, kq = e % BK4;                                \
                As[bf][(kq*4+0)*BMP + m] = ar[i].x;                           \
                As[bf][(kq*4+1)*BMP + m] = ar[i].y;                           \
                As[bf][(kq*4+2)*BMP + m] = ar[i].z;                           \
                As[bf][(kq*4+3)*BMP + m] = ar[i].w;                           \
            }                                                                 \
        }                                                                     \
        _Pragma("unroll")                                                     \
        for (int i = 0; i < NW; i++) {                                        \
            int e = tid + i*NT;                                               \
            if ((BN*BK4) % NT == 0 || e < BN*BK4) {                           \
                int nn = e / BK4, kq = e % BK4;                               \
                Ws[bf][(kq*4+0)*BNP + nn] = wr[i].x;                          \
                Ws[bf][(kq*4+1)*BNP + nn] = wr[i].y;                          \
                Ws[bf][(kq*4+2)*BNP + nn] = wr[i].z;                          \
                Ws[bf][(kq*4+3)*BNP + nn] = wr[i].w;                          \
            }                                                                 \
        }

    LOAD_TILE(0)
    STORE_TILE(0)
    __syncthreads();

    for (int t = 0; t < T; t++) {
        int buf = t & 1;
        if (t + 1 < T) { LOAD_TILE((t+1)*BK) }
        #pragma unroll
        for (int kk = 0; kk < BK; kk++) {
            float av[TM];
            #pragma unroll
            for (int i4 = 0; i4 < TM/4; i4++) {
                if (TM >= 4)
                    *reinterpret_cast<float4*>(&av[i4*4]) =
                        *reinterpret_cast<const float4*>(&As[buf][kk*BMP + ty*TM + i4*4]);
            }
            if (TM == 2) {
                av[0] = As[buf][kk*BMP + ty*2 + 0];
                av[1] = As[buf][kk*BMP + ty*2 + 1];
            }
            ull ad[TM];
            #pragma unroll
            for (int i = 0; i < TM; i++) ad[i] = pack2(av[i]);
            ull bv[TN/2];
            #pragma unroll
            for (int j = 0; j < TN/2; j++)
                bv[j] = *reinterpret_cast<const ull*>(&Ws[buf][kk*BNP + tx*TN + j*2]);
            #pragma unroll
            for (int i = 0; i < TM; i++)
                #pragma unroll
                for (int j = 0; j < TN/2; j++)
                    fma2(acc[i][j], ad[i], bv[j]);
        }
        if (t + 1 < T) { STORE_TILE(buf ^ 1) }
        __syncthreads();
    }
    #undef LOAD_TILE
    #undef STORE_TILE

    #pragma unroll
    for (int i = 0; i < TM; i++) {
        int m = bm + ty*TM + i;
        float ov[TN];
        #pragma unroll
        for (int j = 0; j < TN/2; j++) unpack2(acc[i][j], ov[2*j], ov[2*j+1]);
        if (EP == 1) {
            #pragma unroll
            for (int jj = 0; jj < TN; jj++) {
                int n = bn + tx*TN + jj;
                float v = ov[jj] + bias[n];
                ov[jj] = (v > 20.f) ? v : log1pf(expf(v));
            }
        }
        if (NG) {
            #pragma unroll
            for (int jj = 0; jj < TN; jj++) {
                int n = bn + tx*TN + jj;
                if (n < N) C[(size_t)m*ldc + n] = ov[jj];
            }
        } else {
            #pragma unroll
            for (int j4 = 0; j4 < TN/4; j4++)
                *reinterpret_cast<float4*>(&C[(size_t)m*ldc + bn + tx*TN + j4*4]) =
                    *reinterpret_cast<const float4*>(&ov[j4*4]);
        }
    }
}

/* ---------------- causal depthwise conv + silu -------------------------- */
__global__ __launch_bounds__(256) void conv_silu_kernel(
    const float* __restrict__ xz, const float* __restrict__ cw,
    const float* __restrict__ cb, float* __restrict__ xc)
{
    int idx = blockIdx.x*blockDim.x + threadIdx.x;
    if (idx >= NROWS*DI) return;
    int d = idx % DI, r = idx / DI;
    int b = r / LL, l = r % LL;
    float acc = cb[d];
    #pragma unroll
    for (int j = 0; j < 4; j++) {
        int ls = l - 3 + j;
        if (ls >= 0)
            acc = fmaf(xz[(size_t)(b*LL + ls)*(2*DI) + d], cw[d*4 + j], acc);
    }
    float sig = 1.f / (1.f + expf(-acc));
    xc[idx] = acc * sig;
}

/* ---------------- scan pass 1: inline dt + chunk-local scan ------------- */
/* dt[l,d] = softplus(dbl[l,0:12]·dtw[d,:] + dtb[d]) computed in-kernel.    */
__global__ __launch_bounds__(DI) void scan1_kernel(
    const float* __restrict__ xc, const float* __restrict__ dbl,
    const float* __restrict__ A_log,
    const float* __restrict__ dtw, const float* __restrict__ dtb,
    float* __restrict__ y, float* __restrict__ eend, float* __restrict__ S)
{
    int b = blockIdx.y, ck = blockIdx.x, d = threadIdx.x;
    __shared__ float sB[CL][DS], sC[CL][DS], sdb[CL][13];
    for (int e = d; e < CL*DS; e += DI) {
        int l = e >> 4, n = e & 15;
        const float* row = dbl + (size_t)(b*LL + ck*CL + l)*44;
        sB[l][n] = row[12 + n];
        sC[l][n] = row[28 + n];
    }
    if (d < CL*DR) {
        int l = d / DR, k = d % DR;
        sdb[l][k] = dbl[(size_t)(b*LL + ck*CL + l)*44 + k];
    }
    __syncthreads();
    float w[12];
    #pragma unroll
    for (int i = 0; i < 3; i++)
        *reinterpret_cast<float4*>(&w[i*4]) =
            *reinterpret_cast<const float4*>(&dtw[d*DR + i*4]);
    float bias = dtb[d];
    float cn[DS], h[DS];
    const float* al = A_log + d*DS;
    #pragma unroll
    for (int n = 0; n < DS; n++) { cn[n] = -expf(al[n]) * LOG2E; h[n] = 0.f; }
    float Ss = 0.f;
    int base = (b*LL + ck*CL)*DI + d;
    for (int l = 0; l < CL; l++) {
        float a = bias;
        #pragma unroll
        for (int k = 0; k < 12; k++) a = fmaf(sdb[l][k], w[k], a);
        float dtv = (a > 20.f) ? a : log1pf(expf(a));
        float xcv = xc[base + l*DI];
        Ss += dtv;
        float u = dtv * xcv;
        float acc = 0.f;
        #pragma unroll
        for (int n = 0; n < DS; n++) {
            float e2 = exp2f(dtv * cn[n]);
            h[n] = fmaf(e2, h[n], u * sB[l][n]);
            acc = fmaf(h[n], sC[l][n], acc);
        }
        y[base + l*DI] = acc;
    }
    int si = (b*NC + ck)*DI + d;
    S[si] = Ss;
    #pragma unroll
    for (int n = 0; n < DS; n++) eend[(size_t)si*DS + n] = h[n];
}

/* ---------------- carry propagation across chunks ----------------------- */
__global__ __launch_bounds__(256) void carry_kernel(
    const float* __restrict__ eend, const float* __restrict__ S,
    const float* __restrict__ A_log, float* __restrict__ cin)
{
    int idx = blockIdx.x*blockDim.x + threadIdx.x;
    if (idx >= BB*DI*DS) return;
    int n = idx & 15, d = (idx >> 4) % DI, b = idx / (DI*DS);
    float cf = -expf(A_log[d*DS + n]) * LOG2E;
    float c = 0.f;
    for (int k = 0; k < NC; k++) {
        int si = (b*NC + k)*DI + d;
        cin[(size_t)si*DS + n] = c;
        c = fmaf(exp2f(S[si] * cf), c, eend[(size_t)si*DS + n]);
    }
}

/* ---------------- scan pass 3: inline dt + carry corr + gate ------------ */
__global__ __launch_bounds__(DI) void scan3_kernel(
    const float* __restrict__ dbl, const float* __restrict__ A_log,
    const float* __restrict__ dtw, const float* __restrict__ dtb,
    const float* __restrict__ cin,
    const float* __restrict__ xz, const float* __restrict__ xc,
    const float* __restrict__ Dsk, float* __restrict__ y)
{
    int b = blockIdx.y, ck = blockIdx.x, d = threadIdx.x;
    __shared__ float sC[CL][DS], sdb[CL][13];
    for (int e = d; e < CL*DS; e += DI) {
        int l = e >> 4, n = e & 15;
        sC[l][n] = dbl[(size_t)(b*LL + ck*CL + l)*44 + 28 + n];
    }
    if (d < CL*DR) {
        int l = d / DR, k = d % DR;
        sdb[l][k] = dbl[(size_t)(b*LL + ck*CL + l)*44 + k];
    }
    __syncthreads();
    float w[12];
    #pragma unroll
    for (int i = 0; i < 3; i++)
        *reinterpret_cast<float4*>(&w[i*4]) =
            *reinterpret_cast<const float4*>(&dtw[d*DR + i*4]);
    float bias = dtb[d];
    float cn[DS], ci[DS];
    {
        const float* al = A_log + d*DS;
        #pragma unroll
        for (int n = 0; n < DS; n++) cn[n] = -expf(al[n]) * LOG2E;
    }
    if (ck > 0) {
        const float* cp = cin + (size_t)((b*NC + ck)*DI + d)*DS;
        #pragma unroll
        for (int n = 0; n < DS; n++) ci[n] = cp[n];
    }
    float Dv = Dsk[d];
    int base = (b*LL + ck*CL)*DI + d;
    float tau = 0.f;
    for (int l = 0; l < CL; l++) {
        float a = bias;
        #pragma unroll
        for (int k = 0; k < 12; k++) a = fmaf(sdb[l][k], w[k], a);
        float dtv = (a > 20.f) ? a : log1pf(expf(a));
        tau += dtv;
        float yv = y[base + l*DI];
        if (ck > 0) {
            #pragma unroll
            for (int n = 0; n < DS; n++)
                yv = fmaf(exp2f(tau * cn[n]) * ci[n], sC[l][n], yv);
        }
        yv = fmaf(xc[base + l*DI], Dv, yv);
        int row = b*LL + ck*CL + l;
        float zv = xz[(size_t)row*(2*DI) + DI + d];
        yv *= zv / (1.f + expf(-zv));
        y[base + l*DI] = yv;
    }
}

/* ---------------- host driver ------------------------------------------- */
extern "C" void kernel_launch(void* const* d_in, const int* in_sizes, int n_in,
                              void* d_out, int out_size)
{
    const float* x_img   = (const float*)d_in[0];
    const float* z_img   = (const float*)d_in[1];
    const float* patch_w = (const float*)d_in[2];
    const float* patch_b = (const float*)d_in[3];
    const float* pos_x   = (const float*)d_in[4];
    const float* pos_z   = (const float*)d_in[5];
    const float* ln_w    = (const float*)d_in[6];
    const float* ln_b    = (const float*)d_in[7];
    const float* in_w    = (const float*)d_in[8];
    const float* conv_w  = (const float*)d_in[9];
    const float* conv_b  = (const float*)d_in[10];
    const float* xproj_w = (const float*)d_in[11];
    const float* dt_w    = (const float*)d_in[12];
    const float* dt_b    = (const float*)d_in[13];
    const float* A_log   = (const float*)d_in[14];
    const float* D_skip  = (const float*)d_in[15];
    const float* out_w   = (const float*)d_in[16];
    const float* fnorm_w = (const float*)d_in[17];
    const float* fnorm_b = (const float*)d_in[18];
    float* out = (float*)d_out;

    float *hidden, *res, *hn, *xz, *xc, *dbl, *y, *eend, *S, *cin;
    cudaGetSymbolAddress((void**)&hidden, g_hidden);
    cudaGetSymbolAddress((void**)&res,    g_res);
    cudaGetSymbolAddress((void**)&hn,     g_hn);
    cudaGetSymbolAddress((void**)&xz,     g_xz);
    cudaGetSymbolAddress((void**)&xc,     g_xc);
    cudaGetSymbolAddress((void**)&dbl,    g_dbl);
    cudaGetSymbolAddress((void**)&y,      g_y);
    cudaGetSymbolAddress((void**)&eend,   g_eend);
    cudaGetSymbolAddress((void**)&S,      g_S);
    cudaGetSymbolAddress((void**)&cin,    g_cin);

    patch_kernel<<<NROWS/4, 192>>>(x_img, z_img, patch_w, patch_b,
                                   pos_x, pos_z, hidden, res);

    for (int l = 0; l < DEPTH; l++) {
        addnorm_kernel<<<NROWS, 192>>>(hidden, res, ln_w + l*DM, ln_b + l*DM, hn, 1);

        /* in_proj: (5120,192) @ (768,192)^T -> xz (5120,768) */
        gemm2_kernel<64,128,16,8,8,192,0,false><<<dim3(6, 80), 128>>>(
            hn, DM, in_w + (size_t)l*2*DI*DM, xz, 2*DI, 2*DI, nullptr);

        conv_silu_kernel<<<(NROWS*DI + 255)/256, 256>>>(xz, conv_w + l*DI*4,
                                                        conv_b + l*DI, xc);

        /* x_proj: (5120,384) @ (44,384)^T -> dbl (5120,44), 160 blocks */
        gemm2_kernel<32,64,16,2,8,384,0,true><<<dim3(1, 160), 128>>>(
            xc, DI, xproj_w + (size_t)l*44*DI, dbl, 44, 44, nullptr);

        /* scans with inline dt_proj+softplus */
        scan1_kernel<<<dim3(NC, BB), DI>>>(xc, dbl, A_log + (size_t)l*DI*DS,
                                           dt_w + (size_t)l*DI*DR, dt_b + l*DI,
                                           y, eend, S);
        carry_kernel<<<(BB*DI*DS + 255)/256, 256>>>(eend, S,
                                                    A_log + (size_t)l*DI*DS, cin);
        scan3_kernel<<<dim3(NC, BB), DI>>>(dbl, A_log + (size_t)l*DI*DS,
                                           dt_w + (size_t)l*DI*DR, dt_b + l*DI,
                                           cin, xz, xc, D_skip + l*DI, y);

        /* out_proj: (5120,384) @ (192,384)^T -> hidden (5120,192) */
        gemm2_kernel<64,64,16,4,8,384,0,false><<<dim3(3, 80), 128>>>(
            y, DI, out_w + (size_t)l*DM*DI, hidden, DM, DM, nullptr);
    }

    addnorm_kernel<<<NROWS, 192>>>(hidden, res, fnorm_w, fnorm_b, out, 0);
}

// round 10
// speedup vs baseline: 1.3458x; 1.0096x over previous
#include <cuda_runtime.h>
#include <math.h>

#define BB 16
#define LL 320
#define DM 192
#define DI 384
#define DS 16
#define DR 12
#define DEPTH 24
#define NROWS (BB*LL)      /* 5120 */
#define NC 10
#define CL 32
#define LOG2E 1.4426950408889634f
#define EPSLN 1e-5f

typedef unsigned long long ull;

/* ---------------- scratch (static device globals; no allocation) -------- */
__device__ float g_hidden[NROWS*DM];
__device__ float g_res[NROWS*DM];
__device__ float g_hn[NROWS*DM];
__device__ float g_xz[NROWS*2*DI];
__device__ float g_xc[NROWS*DI];
__device__ float g_dbl[NROWS*44];
__device__ float g_dt[NROWS*DI];
__device__ float g_y[NROWS*DI];
__device__ float g_eend[BB*NC*DI*DS];
__device__ float g_S[BB*NC*DI];
__device__ float g_cin[BB*NC*DI*DS];

__device__ __forceinline__ void fma2(ull &d, ull a, ull b) {
    asm("fma.rn.f32x2 %0, %1, %2, %3;" : "=l"(d) : "l"(a), "l"(b), "l"(d));
}
__device__ __forceinline__ ull pack2(float v) {
    ull d;
    asm("mov.b64 %0, {%1, %1};" : "=l"(d) : "f"(v));
    return d;
}
__device__ __forceinline__ void unpack2(ull v, float &lo, float &hi) {
    asm("mov.b64 {%0, %1}, %2;" : "=f"(lo), "=f"(hi) : "l"(v));
}

/* ---------------- patch embed + pos, zero residual ---------------------- */
__global__ __launch_bounds__(192) void patch_kernel(
    const float* __restrict__ ximg, const float* __restrict__ zimg,
    const float* __restrict__ pw, const float* __restrict__ pb,
    const float* __restrict__ posx, const float* __restrict__ posz,
    float* __restrict__ hidden, float* __restrict__ res)
{
    __shared__ float sp[4][768];
    int tg = blockIdx.x, tid = threadIdx.x;
    for (int i = 0; i < 4; i++) {
        int r = tg*4 + i, b = r / LL, t = r % LL;
        for (int c = tid; c < 768; c += 192) {
            int ch = c >> 8, p = c & 255, py = p >> 4, px = p & 15;
            float v;
            if (t < 64) {
                int ph = (t >> 3)*16 + py, pwi = (t & 7)*16 + px;
                v = zimg[((b*3 + ch)*128 + ph)*128 + pwi];
            } else {
                int tx = t - 64;
                int ph = (tx >> 4)*16 + py, pwi = (tx & 15)*16 + px;
                v = ximg[((b*3 + ch)*256 + ph)*256 + pwi];
            }
            sp[i][c] = v;
        }
    }
    __syncthreads();
    int d = tid;
    float a0 = 0.f, a1 = 0.f, a2 = 0.f, a3 = 0.f;
    const float* wr = pw + d*768;
    for (int c = 0; c < 768; c++) {
        float w = wr[c];
        a0 = fmaf(w, sp[0][c], a0);
        a1 = fmaf(w, sp[1][c], a1);
        a2 = fmaf(w, sp[2][c], a2);
        a3 = fmaf(w, sp[3][c], a3);
    }
    float accs[4] = {a0, a1, a2, a3};
    for (int i = 0; i < 4; i++) {
        int r = tg*4 + i, t = r % LL;
        float pos = (t < 64) ? posz[t*DM + d] : posx[(t - 64)*DM + d];
        hidden[r*DM + d] = accs[i] + pb[d] + pos;
        res[r*DM + d] = 0.f;
    }
}

/* ---------------- fused add + layernorm --------------------------------- */
__global__ __launch_bounds__(192) void addnorm_kernel(
    const float* __restrict__ hid, float* __restrict__ res,
    const float* __restrict__ w, const float* __restrict__ b,
    float* __restrict__ o, int write_res)
{
    int row = blockIdx.x, d = threadIdx.x;
    float v = hid[row*DM + d] + res[row*DM + d];
    if (write_res) res[row*DM + d] = v;
    float s = v, sq = v*v;
    #pragma unroll
    for (int off = 16; off > 0; off >>= 1) {
        s  += __shfl_down_sync(0xffffffffu, s,  off);
        sq += __shfl_down_sync(0xffffffffu, sq, off);
    }
    __shared__ float sh1[6], sh2[6];
    int wid = d >> 5, lane = d & 31;
    if (lane == 0) { sh1[wid] = s; sh2[wid] = sq; }
    __syncthreads();
    float ts = 0.f, tq = 0.f;
    #pragma unroll
    for (int i = 0; i < 6; i++) { ts += sh1[i]; tq += sh2[i]; }
    float mean = ts * (1.f/DM);
    float var  = tq * (1.f/DM) - mean*mean;
    float rs = rsqrtf(var + EPSLN);
    o[row*DM + d] = (v - mean) * rs * w[d] + b[d];
}

/* ---------------- f32x2 packed GEMM: C[M,N] = A[M,K] @ W[N,K]^T ---------- */
template<int BM, int BN, int BK, int TM, int TN, int KT, int EP, bool NG>
__global__ __launch_bounds__((BM/TM)*(BN/TN)) void gemm2_kernel(
    const float* __restrict__ A, int lda,
    const float* __restrict__ W,
    float* __restrict__ C, int ldc,
    int N, const float* __restrict__ bias)
{
    constexpr int NT  = (BM/TM)*(BN/TN);
    constexpr int BK4 = BK/4;
    constexpr int NA  = (BM*BK4 + NT - 1)/NT;
    constexpr int NW  = (BN*BK4 + NT - 1)/NT;
    constexpr int BMP = BM + 4, BNP = BN + 4;
    constexpr int T   = KT/BK;

    __shared__ __align__(16) float As[2][BK*BMP];
    __shared__ __align__(16) float Ws[2][BK*BNP];

    int tid = threadIdx.x;
    int bn = blockIdx.x * BN, bm = blockIdx.y * BM;
    int tx = tid % (BN/TN), ty = tid / (BN/TN);

    ull acc[TM][TN/2];
    #pragma unroll
    for (int i = 0; i < TM; i++)
        #pragma unroll
        for (int j = 0; j < TN/2; j++) acc[i][j] = 0ull;

    float4 ar[NA], wr[NW];

    #define LOAD_TILE(k0)                                                     \
        _Pragma("unroll")                                                     \
        for (int i = 0; i < NA; i++) {                                        \
            int e = tid + i*NT;                                               \
            if ((BM*BK4) % NT == 0 || e < BM*BK4) {                           \
                int m = e / BK4, kq = e % BK4;                                \
                ar[i] = *reinterpret_cast<const float4*>(                     \
                    &A[(size_t)(bm + m)*lda + (k0) + kq*4]);                  \
            }                                                                 \
        }                                                                     \
        _Pragma("unroll")                                                     \
        for (int i = 0; i < NW; i++) {                                        \
            int e = tid + i*NT;                                               \
            if ((BN*BK4) % NT == 0 || e < BN*BK4) {                           \
                int nn = e / BK4, kq = e % BK4;                               \
                if (NG && bn + nn >= N) wr[i] = make_float4(0.f,0.f,0.f,0.f); \
                else wr[i] = *reinterpret_cast<const float4*>(                \
                    &W[(size_t)(bn + nn)*KT + (k0) + kq*4]);                  \
            }                                                                 \
        }

    #define STORE_TILE(bf)                                                    \
        _Pragma("unroll")                                                     \
        for (int i = 0; i < NA; i++) {                                        \
            int e = tid + i*NT;                                               \
            if ((BM*BK4) % NT == 0 || e < BM*BK4) {                           \
                int m = e / BK4, kq = e % BK4;                                \
                As[bf][(kq*4+0)*BMP + m] = ar[i].x;                           \
                As[bf][(kq*4+1)*BMP + m] = ar[i].y;                           \
                As[bf][(kq*4+2)*BMP + m] = ar[i].z;                           \
                As[bf][(kq*4+3)*BMP + m] = ar[i].w;                           \
            }                                                                 \
        }                                                                     \
        _Pragma("unroll")                                                     \
        for (int i = 0; i < NW; i++) {                                        \
            int e = tid + i*NT;                                               \
            if ((BN*BK4) % NT == 0 || e < BN*BK4) {                           \
                int nn = e / BK4, kq = e % BK4;                               \
                Ws[bf][(kq*4+0)*BNP + nn] = wr[i].x;                          \
                Ws[bf][(kq*4+1)*BNP + nn] = wr[i].y;                          \
                Ws[bf][(kq*4+2)*BNP + nn] = wr[i].z;                          \
                Ws[bf][(kq*4+3)*BNP + nn] = wr[i].w;                          \
            }                                                                 \
        }

    LOAD_TILE(0)
    STORE_TILE(0)
    __syncthreads();

    for (int t = 0; t < T; t++) {
        int buf = t & 1;
        if (t + 1 < T) { LOAD_TILE((t+1)*BK) }
        #pragma unroll
        for (int kk = 0; kk < BK; kk++) {
            float av[TM];
            if (TM >= 4) {
                #pragma unroll
                for (int i4 = 0; i4 < TM/4; i4++)
                    *reinterpret_cast<float4*>(&av[i4*4]) =
                        *reinterpret_cast<const float4*>(&As[buf][kk*BMP + ty*TM + i4*4]);
            } else {
                #pragma unroll
                for (int i = 0; i < TM; i++)
                    av[i] = As[buf][kk*BMP + ty*TM + i];
            }
            ull ad[TM];
            #pragma unroll
            for (int i = 0; i < TM; i++) ad[i] = pack2(av[i]);
            ull bv[TN/2];
            #pragma unroll
            for (int j = 0; j < TN/2; j++)
                bv[j] = *reinterpret_cast<const ull*>(&Ws[buf][kk*BNP + tx*TN + j*2]);
            #pragma unroll
            for (int i = 0; i < TM; i++)
                #pragma unroll
                for (int j = 0; j < TN/2; j++)
                    fma2(acc[i][j], ad[i], bv[j]);
        }
        if (t + 1 < T) { STORE_TILE(buf ^ 1) }
        __syncthreads();
    }
    #undef LOAD_TILE
    #undef STORE_TILE

    #pragma unroll
    for (int i = 0; i < TM; i++) {
        int m = bm + ty*TM + i;
        float ov[TN];
        #pragma unroll
        for (int j = 0; j < TN/2; j++) unpack2(acc[i][j], ov[2*j], ov[2*j+1]);
        if (EP == 1) {
            #pragma unroll
            for (int jj = 0; jj < TN; jj++) {
                int n = bn + tx*TN + jj;
                float v = ov[jj] + bias[n];
                ov[jj] = (v > 20.f) ? v : log1pf(expf(v));
            }
        }
        if (NG) {
            #pragma unroll
            for (int jj = 0; jj < TN; jj++) {
                int n = bn + tx*TN + jj;
                if (n < N) C[(size_t)m*ldc + n] = ov[jj];
            }
        } else {
            #pragma unroll
            for (int j4 = 0; j4 < TN/4; j4++)
                *reinterpret_cast<float4*>(&C[(size_t)m*ldc + bn + tx*TN + j4*4]) =
                    *reinterpret_cast<const float4*>(&ov[j4*4]);
        }
    }
}

/* ---------------- causal depthwise conv + silu (float4) ------------------ */
/* one thread -> 4 adjacent channels of one token                            */
__global__ __launch_bounds__(256) void conv_silu_kernel(
    const float* __restrict__ xz, const float* __restrict__ cw,
    const float* __restrict__ cb, float* __restrict__ xc)
{
    int idx = blockIdx.x*blockDim.x + threadIdx.x;
    if (idx >= NROWS*(DI/4)) return;
    int d4 = idx % (DI/4), r = idx / (DI/4);
    int d = d4 * 4;
    int b = r / LL, l = r % LL;

    /* wj[j][c] = cw[(d+c)*4 + j] */
    float wj[4][4];
    #pragma unroll
    for (int c = 0; c < 4; c++) {
        float4 wc = *reinterpret_cast<const float4*>(&cw[(d + c)*4]);
        wj[0][c] = wc.x; wj[1][c] = wc.y; wj[2][c] = wc.z; wj[3][c] = wc.w;
    }
    float4 acc = *reinterpret_cast<const float4*>(&cb[d]);
    #pragma unroll
    for (int j = 0; j < 4; j++) {
        int ls = l - 3 + j;
        if (ls >= 0) {
            float4 x = *reinterpret_cast<const float4*>(
                &xz[(size_t)(b*LL + ls)*(2*DI) + d]);
            acc.x = fmaf(x.x, wj[j][0], acc.x);
            acc.y = fmaf(x.y, wj[j][1], acc.y);
            acc.z = fmaf(x.z, wj[j][2], acc.z);
            acc.w = fmaf(x.w, wj[j][3], acc.w);
        }
    }
    acc.x = acc.x / (1.f + expf(-acc.x));
    acc.y = acc.y / (1.f + expf(-acc.y));
    acc.z = acc.z / (1.f + expf(-acc.z));
    acc.w = acc.w / (1.f + expf(-acc.w));
    *reinterpret_cast<float4*>(&xc[(size_t)r*DI + d]) = acc;
}

/* ---------------- scan pass 1: chunk-local scan ------------------------- */
__global__ __launch_bounds__(DI) void scan1_kernel(
    const float* __restrict__ dt, const float* __restrict__ xc,
    const float* __restrict__ dbl, const float* __restrict__ A_log,
    float* __restrict__ y, float* __restrict__ eend, float* __restrict__ S)
{
    int b = blockIdx.y, ck = blockIdx.x, d = threadIdx.x;
    __shared__ float sB[CL][DS], sC[CL][DS];
    for (int e = d; e < CL*DS; e += DI) {
        int l = e >> 4, n = e & 15;
        const float* row = dbl + (size_t)(b*LL + ck*CL + l)*44;
        sB[l][n] = row[12 + n];
        sC[l][n] = row[28 + n];
    }
    __syncthreads();
    float cn[DS], h[DS];
    const float* al = A_log + d*DS;
    #pragma unroll
    for (int n = 0; n < DS; n++) { cn[n] = -expf(al[n]) * LOG2E; h[n] = 0.f; }
    float Ss = 0.f;
    int base = (b*LL + ck*CL)*DI + d;
    for (int l = 0; l < CL; l++) {
        float dtv = dt[base + l*DI];
        float xcv = xc[base + l*DI];
        Ss += dtv;
        float u = dtv * xcv;
        float acc = 0.f;
        #pragma unroll
        for (int n = 0; n < DS; n++) {
            float e2 = exp2f(dtv * cn[n]);
            h[n] = fmaf(e2, h[n], u * sB[l][n]);
            acc = fmaf(h[n], sC[l][n], acc);
        }
        y[base + l*DI] = acc;
    }
    int si = (b*NC + ck)*DI + d;
    S[si] = Ss;
    #pragma unroll
    for (int n = 0; n < DS; n++) eend[(size_t)si*DS + n] = h[n];
}

/* ---------------- carry propagation across chunks ----------------------- */
__global__ __launch_bounds__(256) void carry_kernel(
    const float* __restrict__ eend, const float* __restrict__ S,
    const float* __restrict__ A_log, float* __restrict__ cin)
{
    int idx = blockIdx.x*blockDim.x + threadIdx.x;
    if (idx >= BB*DI*DS) return;
    int n = idx & 15, d = (idx >> 4) % DI, b = idx / (DI*DS);
    float cf = -expf(A_log[d*DS + n]) * LOG2E;
    float c = 0.f;
    for (int k = 0; k < NC; k++) {
        int si = (b*NC + k)*DI + d;
        cin[(size_t)si*DS + n] = c;
        c = fmaf(exp2f(S[si] * cf), c, eend[(size_t)si*DS + n]);
    }
}

/* ---------------- scan pass 3: carry correction + D skip + z gate ------- */
__global__ __launch_bounds__(DI) void scan3_kernel(
    const float* __restrict__ dt, const float* __restrict__ dbl,
    const float* __restrict__ A_log, const float* __restrict__ cin,
    const float* __restrict__ xz, const float* __restrict__ xc,
    const float* __restrict__ Dsk, float* __restrict__ y)
{
    int b = blockIdx.y, ck = blockIdx.x, d = threadIdx.x;
    __shared__ float sC[CL][DS];
    for (int e = d; e < CL*DS; e += DI) {
        int l = e >> 4, n = e & 15;
        sC[l][n] = dbl[(size_t)(b*LL + ck*CL + l)*44 + 28 + n];
    }
    __syncthreads();
    float cn[DS], ci[DS];
    if (ck > 0) {
        const float* al = A_log + d*DS;
        const float* cp = cin + (size_t)((b*NC + ck)*DI + d)*DS;
        #pragma unroll
        for (int n = 0; n < DS; n++) { cn[n] = -expf(al[n]) * LOG2E; ci[n] = cp[n]; }
    }
    float Dv = Dsk[d];
    int base = (b*LL + ck*CL)*DI + d;
    float tau = 0.f;
    for (int l = 0; l < CL; l++) {
        float dtv = dt[base + l*DI];
        tau += dtv;
        float yv = y[base + l*DI];
        if (ck > 0) {
            #pragma unroll
            for (int n = 0; n < DS; n++)
                yv = fmaf(exp2f(tau * cn[n]) * ci[n], sC[l][n], yv);
        }
        yv = fmaf(xc[base + l*DI], Dv, yv);
        int row = b*LL + ck*CL + l;
        float zv = xz[(size_t)row*(2*DI) + DI + d];
        yv *= zv / (1.f + expf(-zv));
        y[base + l*DI] = yv;
    }
}

/* ---------------- host driver ------------------------------------------- */
extern "C" void kernel_launch(void* const* d_in, const int* in_sizes, int n_in,
                              void* d_out, int out_size)
{
    const float* x_img   = (const float*)d_in[0];
    const float* z_img   = (const float*)d_in[1];
    const float* patch_w = (const float*)d_in[2];
    const float* patch_b = (const float*)d_in[3];
    const float* pos_x   = (const float*)d_in[4];
    const float* pos_z   = (const float*)d_in[5];
    const float* ln_w    = (const float*)d_in[6];
    const float* ln_b    = (const float*)d_in[7];
    const float* in_w    = (const float*)d_in[8];
    const float* conv_w  = (const float*)d_in[9];
    const float* conv_b  = (const float*)d_in[10];
    const float* xproj_w = (const float*)d_in[11];
    const float* dt_w    = (const float*)d_in[12];
    const float* dt_b    = (const float*)d_in[13];
    const float* A_log   = (const float*)d_in[14];
    const float* D_skip  = (const float*)d_in[15];
    const float* out_w   = (const float*)d_in[16];
    const float* fnorm_w = (const float*)d_in[17];
    const float* fnorm_b = (const float*)d_in[18];
    float* out = (float*)d_out;

    float *hidden, *res, *hn, *xz, *xc, *dbl, *dt, *y, *eend, *S, *cin;
    cudaGetSymbolAddress((void**)&hidden, g_hidden);
    cudaGetSymbolAddress((void**)&res,    g_res);
    cudaGetSymbolAddress((void**)&hn,     g_hn);
    cudaGetSymbolAddress((void**)&xz,     g_xz);
    cudaGetSymbolAddress((void**)&xc,     g_xc);
    cudaGetSymbolAddress((void**)&dbl,    g_dbl);
    cudaGetSymbolAddress((void**)&dt,     g_dt);
    cudaGetSymbolAddress((void**)&y,      g_y);
    cudaGetSymbolAddress((void**)&eend,   g_eend);
    cudaGetSymbolAddress((void**)&S,      g_S);
    cudaGetSymbolAddress((void**)&cin,    g_cin);

    patch_kernel<<<NROWS/4, 192>>>(x_img, z_img, patch_w, patch_b,
                                   pos_x, pos_z, hidden, res);

    for (int l = 0; l < DEPTH; l++) {
        addnorm_kernel<<<NROWS, 192>>>(hidden, res, ln_w + l*DM, ln_b + l*DM, hn, 1);

        /* in_proj: (5120,192) @ (768,192)^T -> xz (5120,768) */
        gemm2_kernel<64,128,16,8,8,192,0,false><<<dim3(6, 80), 128>>>(
            hn, DM, in_w + (size_t)l*2*DI*DM, xz, 2*DI, 2*DI, nullptr);

        conv_silu_kernel<<<(NROWS*(DI/4) + 255)/256, 256>>>(xz, conv_w + l*DI*4,
                                                            conv_b + l*DI, xc);

        /* x_proj: (5120,384) @ (44,384)^T -> dbl (5120,44), 160 blocks */
        gemm2_kernel<32,64,16,2,8,384,0,true><<<dim3(1, 160), 128>>>(
            xc, DI, xproj_w + (size_t)l*44*DI, dbl, 44, 44, nullptr);

        /* dt_proj + bias + softplus: (5120,12) @ (384,12)^T -> dt (5120,384) */
        gemm2_kernel<64,64,12,4,8,12,1,false><<<dim3(6, 80), 128>>>(
            dbl, 44, dt_w + (size_t)l*DI*DR, dt, DI, DI, dt_b + l*DI);

        scan1_kernel<<<dim3(NC, BB), DI>>>(dt, xc, dbl, A_log + (size_t)l*DI*DS,
                                           y, eend, S);
        carry_kernel<<<(BB*DI*DS + 255)/256, 256>>>(eend, S,
                                                    A_log + (size_t)l*DI*DS, cin);
        scan3_kernel<<<dim3(NC, BB), DI>>>(dt, dbl, A_log + (size_t)l*DI*DS,
                                           cin, xz, xc, D_skip + l*DI, y);

        /* out_proj: (5120,384) @ (192,384)^T -> hidden (5120,192) */
        gemm2_kernel<64,64,16,4,8,384,0,false><<<dim3(3, 80), 128>>>(
            y, DI, out_w + (size_t)l*DM*DI, hidden, DM, DM, nullptr);
    }

    addnorm_kernel<<<NROWS, 192>>>(hidden, res, fnorm_w, fnorm_b, out, 0);
}